// round 1
// baseline (speedup 1.0000x reference)
#include <cuda_runtime.h>
#include <cuda_bf16.h>
#include <math.h>

// Problem constants (GPTBigCode MQA)
#define BB 2
#define SS 2048
#define DD 2048
#define HH 16
#define HDIM 128
#define NQKV (HH * HDIM + 2 * HDIM)   // 2304
#define MM (BB * SS)                  // 4096

// Scratch (device globals — no allocation allowed)
__device__ float g_qkv[MM * NQKV];    // [4096, 2304]
__device__ float g_att[MM * DD];      // [4096, 2048]

// ---------------------------------------------------------------------------
// SGEMM with bias: C[M,N] = A[M,K] @ B[K,N] + bias[N]
// BM=BN=128, BK=8, 256 threads, 8x8 microtile. M%128==0, N%128==0, K%8==0.
// ---------------------------------------------------------------------------
__global__ __launch_bounds__(256) void sgemm_bias_kernel(
    const float* __restrict__ A, const float* __restrict__ Bm,
    const float* __restrict__ bias, float* __restrict__ C,
    int M, int N, int K)
{
    const int BM = 128, BN = 128, BK = 8;
    __shared__ float As[BK][BM];
    __shared__ float Bs[BK][BN];

    const int tid = threadIdx.x;
    const int bRow = blockIdx.y;   // M tile
    const int bCol = blockIdx.x;   // N tile

    // A load mapping: 128x8 tile, each thread one float4
    const int aRow = tid >> 1;            // 0..127
    const int aCol = (tid & 1) * 4;       // 0 or 4
    // B load mapping: 8x128 tile
    const int bRowL = tid >> 5;           // 0..7
    const int bColL = (tid & 31) * 4;     // 0..124

    const int ty = tid >> 4;              // 0..15
    const int tx = tid & 15;              // 0..15

    const float* Aptr = A + (size_t)(bRow * BM + aRow) * K + aCol;
    const float* Bptr = Bm + (size_t)bRowL * N + bCol * BN + bColL;

    float acc[8][8];
#pragma unroll
    for (int i = 0; i < 8; i++)
#pragma unroll
        for (int j = 0; j < 8; j++) acc[i][j] = 0.0f;

    for (int k0 = 0; k0 < K; k0 += BK) {
        // load A tile (transposed into As)
        float4 av = *reinterpret_cast<const float4*>(Aptr + k0);
        As[aCol + 0][aRow] = av.x;
        As[aCol + 1][aRow] = av.y;
        As[aCol + 2][aRow] = av.z;
        As[aCol + 3][aRow] = av.w;
        // load B tile
        float4 bv = *reinterpret_cast<const float4*>(Bptr + (size_t)k0 * N);
        *reinterpret_cast<float4*>(&Bs[bRowL][bColL]) = bv;
        __syncthreads();

#pragma unroll
        for (int k = 0; k < BK; k++) {
            float ar[8], br[8];
#pragma unroll
            for (int i = 0; i < 8; i++) ar[i] = As[k][ty * 8 + i];
#pragma unroll
            for (int j = 0; j < 8; j++) br[j] = Bs[k][tx * 8 + j];
#pragma unroll
            for (int i = 0; i < 8; i++)
#pragma unroll
                for (int j = 0; j < 8; j++)
                    acc[i][j] = fmaf(ar[i], br[j], acc[i][j]);
        }
        __syncthreads();
    }

    // epilogue: add bias, store
    const int col0 = bCol * BN + tx * 8;
    float bb0[8];
#pragma unroll
    for (int j = 0; j < 8; j++) bb0[j] = bias[col0 + j];

#pragma unroll
    for (int i = 0; i < 8; i++) {
        const int row = bRow * BM + ty * 8 + i;
        float4 o0, o1;
        o0.x = acc[i][0] + bb0[0];
        o0.y = acc[i][1] + bb0[1];
        o0.z = acc[i][2] + bb0[2];
        o0.w = acc[i][3] + bb0[3];
        o1.x = acc[i][4] + bb0[4];
        o1.y = acc[i][5] + bb0[5];
        o1.z = acc[i][6] + bb0[6];
        o1.w = acc[i][7] + bb0[7];
        *reinterpret_cast<float4*>(&C[(size_t)row * N + col0]) = o0;
        *reinterpret_cast<float4*>(&C[(size_t)row * N + col0 + 4]) = o1;
    }
}

// ---------------------------------------------------------------------------
// MQA causal flash attention, fp32 SIMT.
// One warp per query row. Block = 8 warps = 8 consecutive q rows.
// K/V tiles (64 keys x 128 dims each) staged in dynamic smem (64 KB).
// grid = (S/8, H, B)
// ---------------------------------------------------------------------------
__global__ __launch_bounds__(256) void mqa_attn_kernel(
    const float* __restrict__ qkv, float* __restrict__ out)
{
    const int BNK = 64;
    extern __shared__ float sm[];
    float* Ks = sm;                 // [64][128]
    float* Vs = sm + BNK * HDIM;    // [64][128]

    const int tid  = threadIdx.x;
    const int warp = tid >> 5;
    const int lane = tid & 31;
    const int b = blockIdx.z;
    const int h = blockIdx.y;
    const int q = blockIdx.x * 8 + warp;
    const int q_max = blockIdx.x * 8 + 7;

    const float scale = 1.0f / sqrtf((float)HDIM);

    // load q fragment (lane owns dims lane*4 .. lane*4+3), pre-scaled
    const size_t qkv_row = (size_t)(b * SS + q) * NQKV;
    float4 qv = *reinterpret_cast<const float4*>(&qkv[qkv_row + h * HDIM + lane * 4]);
    qv.x *= scale; qv.y *= scale; qv.z *= scale; qv.w *= scale;

    float m = -INFINITY, l = 0.0f;
    float o0 = 0.f, o1 = 0.f, o2 = 0.f, o3 = 0.f;

    for (int t0 = 0; t0 <= q_max; t0 += BNK) {
        __syncthreads();
        // cooperative load of K/V tile: 2048 float4 each, 256 threads -> 8 each
#pragma unroll
        for (int it = 0; it < 8; it++) {
            int idx = tid + it * 256;           // 0..2047
            int row = idx >> 5;                 // 0..63
            int cf4 = (idx & 31) * 4;           // 0..124
            const size_t src = (size_t)(b * SS + t0 + row) * NQKV;
            float4 kvk = *reinterpret_cast<const float4*>(&qkv[src + HH * HDIM + cf4]);
            float4 kvv = *reinterpret_cast<const float4*>(&qkv[src + HH * HDIM + HDIM + cf4]);
            *reinterpret_cast<float4*>(&Ks[row * HDIM + cf4]) = kvk;
            *reinterpret_cast<float4*>(&Vs[row * HDIM + cf4]) = kvv;
        }
        __syncthreads();

        int nvalid = q - t0 + 1;
        if (nvalid > BNK) nvalid = BNK;
        if (nvalid <= 0) continue;

        // pass 1: scores (scaled) for keys [0, nvalid)
        float s0 = -INFINITY, s1 = -INFINITY;
        for (int kk = 0; kk < nvalid; kk++) {
            float4 kv = *reinterpret_cast<const float4*>(&Ks[kk * HDIM + lane * 4]);
            float p = qv.x * kv.x + qv.y * kv.y + qv.z * kv.z + qv.w * kv.w;
            p += __shfl_xor_sync(0xffffffffu, p, 16);
            p += __shfl_xor_sync(0xffffffffu, p, 8);
            p += __shfl_xor_sync(0xffffffffu, p, 4);
            p += __shfl_xor_sync(0xffffffffu, p, 2);
            p += __shfl_xor_sync(0xffffffffu, p, 1);
            if ((kk & 31) == lane) { if (kk < 32) s0 = p; else s1 = p; }
        }

        // tile max
        float tm = fmaxf(s0, s1);
        tm = fmaxf(tm, __shfl_xor_sync(0xffffffffu, tm, 16));
        tm = fmaxf(tm, __shfl_xor_sync(0xffffffffu, tm, 8));
        tm = fmaxf(tm, __shfl_xor_sync(0xffffffffu, tm, 4));
        tm = fmaxf(tm, __shfl_xor_sync(0xffffffffu, tm, 2));
        tm = fmaxf(tm, __shfl_xor_sync(0xffffffffu, tm, 1));

        float m_new = fmaxf(m, tm);
        float corr = __expf(m - m_new);   // m=-inf on first tile -> 0
        o0 *= corr; o1 *= corr; o2 *= corr; o3 *= corr;
        l *= corr;

        float p0 = __expf(s0 - m_new);    // s=-inf -> 0
        float p1 = __expf(s1 - m_new);
        float ls = p0 + p1;
        ls += __shfl_xor_sync(0xffffffffu, ls, 16);
        ls += __shfl_xor_sync(0xffffffffu, ls, 8);
        ls += __shfl_xor_sync(0xffffffffu, ls, 4);
        ls += __shfl_xor_sync(0xffffffffu, ls, 2);
        ls += __shfl_xor_sync(0xffffffffu, ls, 1);
        l += ls;
        m = m_new;

        // pass 2: P @ V
        for (int kk = 0; kk < nvalid; kk++) {
            float psrc = (kk < 32) ? p0 : p1;
            float p = __shfl_sync(0xffffffffu, psrc, kk & 31);
            float4 vv = *reinterpret_cast<const float4*>(&Vs[kk * HDIM + lane * 4]);
            o0 = fmaf(p, vv.x, o0);
            o1 = fmaf(p, vv.y, o1);
            o2 = fmaf(p, vv.z, o2);
            o3 = fmaf(p, vv.w, o3);
        }
    }

    const float inv = 1.0f / l;
    float4 res;
    res.x = o0 * inv; res.y = o1 * inv; res.z = o2 * inv; res.w = o3 * inv;
    *reinterpret_cast<float4*>(&out[(size_t)(b * SS + q) * DD + h * HDIM + lane * 4]) = res;
}

// ---------------------------------------------------------------------------
extern "C" void kernel_launch(void* const* d_in, const int* in_sizes, int n_in,
                              void* d_out, int out_size)
{
    const float* hidden = (const float*)d_in[0];   // [B,S,D]
    const float* W_attn = (const float*)d_in[1];   // [D, 2304]
    const float* b_attn = (const float*)d_in[2];   // [2304]
    const float* W_proj = (const float*)d_in[3];   // [D, D]
    const float* b_proj = (const float*)d_in[4];   // [D]
    // d_in[5] = attention_mask (causal tril) — implemented analytically
    float* out = (float*)d_out;

    float* qkv;  cudaGetSymbolAddress((void**)&qkv, g_qkv);
    float* att;  cudaGetSymbolAddress((void**)&att, g_att);

    // allow 64 KB dynamic smem for attention (idempotent, not a stream op)
    cudaFuncSetAttribute(mqa_attn_kernel,
                         cudaFuncAttributeMaxDynamicSharedMemorySize, 64 * 128 * 2 * 4);

    // 1) QKV GEMM: [4096,2048] @ [2048,2304] + b_attn
    {
        dim3 grid(NQKV / 128, MM / 128);
        sgemm_bias_kernel<<<grid, 256>>>(hidden, W_attn, b_attn, qkv, MM, NQKV, DD);
    }

    // 2) MQA causal flash attention
    {
        dim3 grid(SS / 8, HH, BB);
        mqa_attn_kernel<<<grid, 256, 64 * 128 * 2 * 4>>>(qkv, att);
    }

    // 3) Projection GEMM: [4096,2048] @ [2048,2048] + b_proj
    {
        dim3 grid(DD / 128, MM / 128);
        sgemm_bias_kernel<<<grid, 256>>>(att, W_proj, b_proj, out, MM, DD, DD);
    }
}

// round 2
// speedup vs baseline: 1.9492x; 1.9492x over previous
#include <cuda_runtime.h>
#include <cuda_bf16.h>
#include <math.h>

// Problem constants (GPTBigCode MQA)
#define BB 2
#define SS 2048
#define DD 2048
#define HH 16
#define HDIM 128
#define NQKV (HH * HDIM + 2 * HDIM)   // 2304
#define MM (BB * SS)                  // 4096

// Scratch (device globals — no allocation allowed)
__device__ float g_qkv[MM * NQKV];    // [4096, 2304]
__device__ float g_att[MM * DD];      // [4096, 2048]

// ---------------------------------------------------------------------------
// SGEMM with bias: C[M,N] = A[M,K] @ B[K,N] + bias[N]
// BM=BN=128, BK=8, 256 threads, 8x8 microtile.
// ---------------------------------------------------------------------------
__global__ __launch_bounds__(256) void sgemm_bias_kernel(
    const float* __restrict__ A, const float* __restrict__ Bm,
    const float* __restrict__ bias, float* __restrict__ C,
    int M, int N, int K)
{
    const int BM = 128, BN = 128, BK = 8;
    __shared__ float As[BK][BM];
    __shared__ float Bs[BK][BN];

    const int tid = threadIdx.x;
    const int bRow = blockIdx.y;
    const int bCol = blockIdx.x;

    const int aRow = tid >> 1;
    const int aCol = (tid & 1) * 4;
    const int bRowL = tid >> 5;
    const int bColL = (tid & 31) * 4;

    const int ty = tid >> 4;
    const int tx = tid & 15;

    const float* Aptr = A + (size_t)(bRow * BM + aRow) * K + aCol;
    const float* Bptr = Bm + (size_t)bRowL * N + bCol * BN + bColL;

    float acc[8][8];
#pragma unroll
    for (int i = 0; i < 8; i++)
#pragma unroll
        for (int j = 0; j < 8; j++) acc[i][j] = 0.0f;

    for (int k0 = 0; k0 < K; k0 += BK) {
        float4 av = *reinterpret_cast<const float4*>(Aptr + k0);
        As[aCol + 0][aRow] = av.x;
        As[aCol + 1][aRow] = av.y;
        As[aCol + 2][aRow] = av.z;
        As[aCol + 3][aRow] = av.w;
        float4 bv = *reinterpret_cast<const float4*>(Bptr + (size_t)k0 * N);
        *reinterpret_cast<float4*>(&Bs[bRowL][bColL]) = bv;
        __syncthreads();

#pragma unroll
        for (int k = 0; k < BK; k++) {
            float ar[8], br[8];
#pragma unroll
            for (int i = 0; i < 8; i++) ar[i] = As[k][ty * 8 + i];
#pragma unroll
            for (int j = 0; j < 8; j++) br[j] = Bs[k][tx * 8 + j];
#pragma unroll
            for (int i = 0; i < 8; i++)
#pragma unroll
                for (int j = 0; j < 8; j++)
                    acc[i][j] = fmaf(ar[i], br[j], acc[i][j]);
        }
        __syncthreads();
    }

    const int col0 = bCol * BN + tx * 8;
    float bb0[8];
#pragma unroll
    for (int j = 0; j < 8; j++) bb0[j] = bias[col0 + j];

#pragma unroll
    for (int i = 0; i < 8; i++) {
        const int row = bRow * BM + ty * 8 + i;
        float4 o0, o1;
        o0.x = acc[i][0] + bb0[0];
        o0.y = acc[i][1] + bb0[1];
        o0.z = acc[i][2] + bb0[2];
        o0.w = acc[i][3] + bb0[3];
        o1.x = acc[i][4] + bb0[4];
        o1.y = acc[i][5] + bb0[5];
        o1.z = acc[i][6] + bb0[6];
        o1.w = acc[i][7] + bb0[7];
        *reinterpret_cast<float4*>(&C[(size_t)row * N + col0]) = o0;
        *reinterpret_cast<float4*>(&C[(size_t)row * N + col0 + 4]) = o1;
    }
}

// ---------------------------------------------------------------------------
// MQA flash attention v2 — GEMM-style, exploits shared K/V across all heads.
//
// One block (256 thr, 16x16) handles ROWS=128 score rows = 16 heads x 8 q rows
// of one batch, tiling keys by BK=128. Both QK^T and PV are 128x128x128
// register-tiled GEMMs (8x8 microtile per thread).
//
// Fragment mapping: thread (ty,tx): rows ty*8+i (head=ty, qi=i),
// cols tx+16*j (interleaved) -> all GEMM-phase smem reads conflict-free.
//
// smem (dynamic, 198 KB): Qs[d][132] (transposed Q), KPs[d][132] (transposed K,
// reused as P[row][128] after QK), Vs[k][132].
// grid = (S/8, B)
// ---------------------------------------------------------------------------
#define AT_BK 128
#define QS_STR 132

__global__ __launch_bounds__(256, 1) void mqa_attn_v2(
    const float* __restrict__ qkv, float* __restrict__ out)
{
    extern __shared__ float sm[];
    float* Qs  = sm;                        // [128][132] Q transposed [d][row]
    float* KPs = sm + 128 * QS_STR;         // K: [d][132] / P: [row][128]
    float* Vs  = KPs + 128 * QS_STR;        // [k][132]

    const int tid = threadIdx.x;
    const int tx = tid & 15;
    const int ty = tid >> 4;
    const int b = blockIdx.y;
    const int q0 = blockIdx.x * 8;
    const float scale = 0.08838834764831845f;  // 1/sqrt(128)

    // ---- load Q tile, transposed + pre-scaled ----
    // column-major mapping: lanes vary along row r -> conflict-free stores
#pragma unroll
    for (int it = 0; it < 16; ++it) {
        int idx = tid + it * 256;           // 0..4095
        int r = idx & 127;                  // row = h*8+qi
        int c = idx >> 7;                   // float4 column (d0 = 4c)
        int h = r >> 3, qi = r & 7;
        float4 v = *reinterpret_cast<const float4*>(
            &qkv[(size_t)(b * SS + q0 + qi) * NQKV + h * HDIM + 4 * c]);
        Qs[(4 * c + 0) * QS_STR + r] = v.x * scale;
        Qs[(4 * c + 1) * QS_STR + r] = v.y * scale;
        Qs[(4 * c + 2) * QS_STR + r] = v.z * scale;
        Qs[(4 * c + 3) * QS_STR + r] = v.w * scale;
    }

    // per-thread flash state
    float m[8], l[8], O[8][8];
#pragma unroll
    for (int i = 0; i < 8; i++) {
        m[i] = -INFINITY; l[i] = 0.0f;
#pragma unroll
        for (int j = 0; j < 8; j++) O[i][j] = 0.0f;
    }

    const int q_max = q0 + 7;
    const int ntiles = q_max / AT_BK + 1;

    for (int t = 0; t < ntiles; ++t) {
        const int t0 = t * AT_BK;
        __syncthreads();   // Ps/Vs from previous iter fully consumed

        // ---- load K tile (transposed, column-major mapping) ----
#pragma unroll
        for (int it = 0; it < 16; ++it) {
            int idx = tid + it * 256;
            int k = idx & 127;
            int c = idx >> 7;
            float4 v = *reinterpret_cast<const float4*>(
                &qkv[(size_t)(b * SS + t0 + k) * NQKV + HH * HDIM + 4 * c]);
            KPs[(4 * c + 0) * QS_STR + k] = v.x;
            KPs[(4 * c + 1) * QS_STR + k] = v.y;
            KPs[(4 * c + 2) * QS_STR + k] = v.z;
            KPs[(4 * c + 3) * QS_STR + k] = v.w;
        }
        // ---- load V tile (natural [k][d], row-major mapping, coalesced) ----
#pragma unroll
        for (int it = 0; it < 16; ++it) {
            int idx = tid + it * 256;
            int k = idx >> 5;
            int c = idx & 31;
            float4 v = *reinterpret_cast<const float4*>(
                &qkv[(size_t)(b * SS + t0 + k) * NQKV + HH * HDIM + HDIM + 4 * c]);
            *reinterpret_cast<float4*>(&Vs[k * QS_STR + 4 * c]) = v;
        }
        __syncthreads();

        // ---- QK^T: s[i][j] = sum_d Q[row][d] * K[key][d] ----
        float s[8][8];
#pragma unroll
        for (int i = 0; i < 8; i++)
#pragma unroll
            for (int j = 0; j < 8; j++) s[i][j] = 0.0f;

#pragma unroll 4
        for (int d = 0; d < 128; ++d) {
            float a[8], bfr[8];
            float4 a0 = *reinterpret_cast<const float4*>(&Qs[d * QS_STR + ty * 8]);
            float4 a1 = *reinterpret_cast<const float4*>(&Qs[d * QS_STR + ty * 8 + 4]);
            a[0] = a0.x; a[1] = a0.y; a[2] = a0.z; a[3] = a0.w;
            a[4] = a1.x; a[5] = a1.y; a[6] = a1.z; a[7] = a1.w;
#pragma unroll
            for (int j = 0; j < 8; j++) bfr[j] = KPs[d * QS_STR + tx + 16 * j];
#pragma unroll
            for (int i = 0; i < 8; i++)
#pragma unroll
                for (int j = 0; j < 8; j++)
                    s[i][j] = fmaf(a[i], bfr[j], s[i][j]);
        }

        // ---- causal mask (only last tile can straddle the diagonal) ----
        if (t == ntiles - 1) {
#pragma unroll
            for (int i = 0; i < 8; i++)
#pragma unroll
                for (int j = 0; j < 8; j++)
                    if (t0 + tx + 16 * j > q0 + i) s[i][j] = -1.0e30f;
        }

        // ---- online softmax (rows owned by 16-lane groups: same ty) ----
        float corr[8];
#pragma unroll
        for (int i = 0; i < 8; i++) {
            float mx = s[i][0];
#pragma unroll
            for (int j = 1; j < 8; j++) mx = fmaxf(mx, s[i][j]);
            mx = fmaxf(mx, __shfl_xor_sync(0xffffffffu, mx, 1));
            mx = fmaxf(mx, __shfl_xor_sync(0xffffffffu, mx, 2));
            mx = fmaxf(mx, __shfl_xor_sync(0xffffffffu, mx, 4));
            mx = fmaxf(mx, __shfl_xor_sync(0xffffffffu, mx, 8));
            float m_new = fmaxf(m[i], mx);
            corr[i] = __expf(m[i] - m_new);
            m[i] = m_new;
            float sum = 0.0f;
#pragma unroll
            for (int j = 0; j < 8; j++) {
                float p = __expf(s[i][j] - m_new);
                s[i][j] = p;
                sum += p;
            }
            sum += __shfl_xor_sync(0xffffffffu, sum, 1);
            sum += __shfl_xor_sync(0xffffffffu, sum, 2);
            sum += __shfl_xor_sync(0xffffffffu, sum, 4);
            sum += __shfl_xor_sync(0xffffffffu, sum, 8);
            l[i] = l[i] * corr[i] + sum;
#pragma unroll
            for (int j = 0; j < 8; j++) O[i][j] *= corr[i];
        }

        // ---- write P into KPs region (K fully consumed) ----
        __syncthreads();
#pragma unroll
        for (int i = 0; i < 8; i++)
#pragma unroll
            for (int j = 0; j < 8; j++)
                KPs[(ty * 8 + i) * 128 + tx + 16 * j] = s[i][j];
        __syncthreads();

        // ---- PV: O[row][d] += P[row][k] * V[k][d] ----
#pragma unroll 4
        for (int k = 0; k < 128; ++k) {
            float a[8], bfr[8];
#pragma unroll
            for (int i = 0; i < 8; i++) a[i] = KPs[(ty * 8 + i) * 128 + k];
#pragma unroll
            for (int j = 0; j < 8; j++) bfr[j] = Vs[k * QS_STR + tx + 16 * j];
#pragma unroll
            for (int i = 0; i < 8; i++)
#pragma unroll
                for (int j = 0; j < 8; j++)
                    O[i][j] = fmaf(a[i], bfr[j], O[i][j]);
        }
    }

    // ---- epilogue: normalize + store ----
#pragma unroll
    for (int i = 0; i < 8; i++) {
        float inv = 1.0f / l[i];
        size_t base = (size_t)(b * SS + q0 + i) * DD + ty * HDIM + tx;
#pragma unroll
        for (int j = 0; j < 8; j++)
            out[base + 16 * j] = O[i][j] * inv;
    }
}

// ---------------------------------------------------------------------------
extern "C" void kernel_launch(void* const* d_in, const int* in_sizes, int n_in,
                              void* d_out, int out_size)
{
    const float* hidden = (const float*)d_in[0];   // [B,S,D]
    const float* W_attn = (const float*)d_in[1];   // [D, 2304]
    const float* b_attn = (const float*)d_in[2];   // [2304]
    const float* W_proj = (const float*)d_in[3];   // [D, D]
    const float* b_proj = (const float*)d_in[4];   // [D]
    float* out = (float*)d_out;

    float* qkv;  cudaGetSymbolAddress((void**)&qkv, g_qkv);
    float* att;  cudaGetSymbolAddress((void**)&att, g_att);

    const int attn_smem = 128 * QS_STR * 3 * sizeof(float);  // 202,752 B
    cudaFuncSetAttribute(mqa_attn_v2,
                         cudaFuncAttributeMaxDynamicSharedMemorySize, attn_smem);

    // 1) QKV GEMM: [4096,2048] @ [2048,2304] + b_attn
    {
        dim3 grid(NQKV / 128, MM / 128);
        sgemm_bias_kernel<<<grid, 256>>>(hidden, W_attn, b_attn, qkv, MM, NQKV, DD);
    }

    // 2) MQA causal flash attention (all heads per block)
    {
        dim3 grid(SS / 8, BB);
        mqa_attn_v2<<<grid, 256, attn_smem>>>(qkv, att);
    }

    // 3) Projection GEMM: [4096,2048] @ [2048,2048] + b_proj
    {
        dim3 grid(DD / 128, MM / 128);
        sgemm_bias_kernel<<<grid, 256>>>(att, W_proj, b_proj, out, MM, DD, DD);
    }
}

// round 4
// speedup vs baseline: 2.7934x; 1.4331x over previous
#include <cuda_runtime.h>
#include <cuda_bf16.h>
#include <mma.h>
#include <math.h>
#include <cstdint>

using namespace nvcuda;

// Problem constants (GPTBigCode MQA)
#define BB 2
#define SS 2048
#define DD 2048
#define HH 16
#define HDIM 128
#define NQKV (HH * HDIM + 2 * HDIM)   // 2304
#define MM (BB * SS)                  // 4096

// ---------------- scratch (device globals; no allocation allowed) ----------
__device__ float g_qkv[MM * NQKV];                    // [4096, 2304]
__device__ float g_att[MM * DD];                      // [4096, 2048]
__device__ __nv_bfloat16 g_Xhi[MM * DD];              // hidden split [M,K]
__device__ __nv_bfloat16 g_Xlo[MM * DD];
__device__ __nv_bfloat16 g_WaThi[NQKV * DD];          // W_attn^T split [N,K]
__device__ __nv_bfloat16 g_WaTlo[NQKV * DD];
__device__ __nv_bfloat16 g_WpThi[DD * DD];            // W_proj^T split [N,K]
__device__ __nv_bfloat16 g_WpTlo[DD * DD];
__device__ __nv_bfloat16 g_AThi[MM * DD];             // attention out split [M,K]
__device__ __nv_bfloat16 g_ATlo[MM * DD];

// ---------------- helpers ---------------------------------------------------
__device__ __forceinline__ uint32_t smem_u32(const void* p) {
    uint32_t a;
    asm("{ .reg .u64 t; cvta.to.shared.u64 t, %1; cvt.u32.u64 %0, t; }" : "=r"(a) : "l"(p));
    return a;
}
__device__ __forceinline__ void cp_async16(uint32_t dst, const void* src) {
    asm volatile("cp.async.cg.shared.global [%0], [%1], 16;" :: "r"(dst), "l"(src));
}
__device__ __forceinline__ void cp_commit() {
    asm volatile("cp.async.commit_group;" ::: "memory");
}
template <int N>
__device__ __forceinline__ void cp_wait() {
    asm volatile("cp.async.wait_group %0;" :: "n"(N) : "memory");
}

// ---------------------------------------------------------------------------
// split: fp32 -> (bf16 hi, bf16 lo), flat
// ---------------------------------------------------------------------------
__global__ __launch_bounds__(256) void split_kernel(
    const float* __restrict__ X, __nv_bfloat16* __restrict__ hi,
    __nv_bfloat16* __restrict__ lo, int n)
{
    int i = (blockIdx.x * 256 + threadIdx.x) * 4;
    if (i >= n) return;
    float4 v = *reinterpret_cast<const float4*>(&X[i]);
    __nv_bfloat16 h0 = __float2bfloat16(v.x), h1 = __float2bfloat16(v.y);
    __nv_bfloat16 h2 = __float2bfloat16(v.z), h3 = __float2bfloat16(v.w);
    __nv_bfloat16 l0 = __float2bfloat16(v.x - __bfloat162float(h0));
    __nv_bfloat16 l1 = __float2bfloat16(v.y - __bfloat162float(h1));
    __nv_bfloat16 l2 = __float2bfloat16(v.z - __bfloat162float(h2));
    __nv_bfloat16 l3 = __float2bfloat16(v.w - __bfloat162float(h3));
    __nv_bfloat162 hp0 = {h0, h1}, hp1 = {h2, h3}, lp0 = {l0, l1}, lp1 = {l2, l3};
    *reinterpret_cast<__nv_bfloat162*>(&hi[i]) = hp0;
    *reinterpret_cast<__nv_bfloat162*>(&hi[i + 2]) = hp1;
    *reinterpret_cast<__nv_bfloat162*>(&lo[i]) = lp0;
    *reinterpret_cast<__nv_bfloat162*>(&lo[i + 2]) = lp1;
}

// ---------------------------------------------------------------------------
// split + transpose: W[K,N] fp32 -> T{hi,lo}[N,K] bf16
// ---------------------------------------------------------------------------
__global__ __launch_bounds__(256) void split_transpose_kernel(
    const float* __restrict__ W, __nv_bfloat16* __restrict__ Thi,
    __nv_bfloat16* __restrict__ Tlo, int K, int N)
{
    __shared__ float t[32][33];
    int tx = threadIdx.x, ty = threadIdx.y;
    int n0 = blockIdx.x * 32, k0 = blockIdx.y * 32;
#pragma unroll
    for (int i = 0; i < 4; i++)
        t[ty + 8 * i][tx] = W[(size_t)(k0 + ty + 8 * i) * N + n0 + tx];
    __syncthreads();
#pragma unroll
    for (int i = 0; i < 4; i++) {
        float v = t[tx][ty + 8 * i];
        __nv_bfloat16 h = __float2bfloat16(v);
        __nv_bfloat16 l = __float2bfloat16(v - __bfloat162float(h));
        size_t o = (size_t)(n0 + ty + 8 * i) * K + k0 + tx;
        Thi[o] = h;
        Tlo[o] = l;
    }
}

// ---------------------------------------------------------------------------
// wmma bf16 3-term split GEMM + bias:
// C[M,N] = (Ahi+Alo)[M,K] @ (Bhi+Blo)[N,K]^T + bias  (drop lo*lo term)
// CTA tile 128x128, BK=32, 8 warps (warp tile 32x64), cp.async double buffer.
// grid = (N/128, M/128), 256 threads.
// ---------------------------------------------------------------------------
#define BK 32
#define LDT 40                       // smem tile ld (halves): 32 + 8 pad
#define TILE_HB (128 * LDT)          // halves per tile
#define TILE_BYTES (TILE_HB * 2)     // 10240 B
#define BUF_BYTES (4 * TILE_BYTES)   // Ahi,Alo,Bhi,Blo = 40960 B
#define EPI_LD 136                   // epilogue float ld

__global__ __launch_bounds__(256, 1)
void wmma_gemm_bias(const __nv_bfloat16* __restrict__ Ahi,
                    const __nv_bfloat16* __restrict__ Alo,
                    const __nv_bfloat16* __restrict__ Bhi,
                    const __nv_bfloat16* __restrict__ Blo,
                    const float* __restrict__ bias, float* __restrict__ C,
                    int M, int N, int K)
{
    extern __shared__ char sm[];
    const uint32_t smb = smem_u32(sm);
    const int tid = threadIdx.x;
    const int wid = tid >> 5;
    const int ntile = blockIdx.x, mtile = blockIdx.y;

    const int warp_m = (wid >> 1) * 32;   // 0,32,64,96
    const int warp_n = (wid & 1) * 64;    // 0,64

    const __nv_bfloat16* srcs[4] = {
        Ahi + (size_t)mtile * 128 * K, Alo + (size_t)mtile * 128 * K,
        Bhi + (size_t)ntile * 128 * K, Blo + (size_t)ntile * 128 * K };

    // issue cp.async for all 4 tiles of buffer b at k-offset k0
    auto issue_load = [&](int b, int k0) {
        const uint32_t bufb = smb + b * BUF_BYTES;
#pragma unroll
        for (int t = 0; t < 4; t++) {
            const __nv_bfloat16* s = srcs[t];
            const uint32_t tb = bufb + t * TILE_BYTES;
#pragma unroll
            for (int it = 0; it < 2; it++) {
                int idx = tid + it * 256;       // 0..511
                int row = idx >> 2;             // 0..127
                int ch = idx & 3;               // 16B chunk within 64B row
                cp_async16(tb + (row * LDT + ch * 8) * 2,
                           s + (size_t)row * K + k0 + ch * 8);
            }
        }
        cp_commit();
    };

    wmma::fragment<wmma::accumulator, 16, 16, 16, float> acc[2][4];
#pragma unroll
    for (int i = 0; i < 2; i++)
#pragma unroll
        for (int j = 0; j < 4; j++) wmma::fill_fragment(acc[i][j], 0.0f);

    const int niter = K / BK;
    issue_load(0, 0);

    for (int iter = 0; iter < niter; iter++) {
        const int buf = iter & 1;
        if (iter + 1 < niter) {
            issue_load(buf ^ 1, (iter + 1) * BK);
            cp_wait<1>();
        } else {
            cp_wait<0>();
        }
        __syncthreads();

        const __nv_bfloat16* base = reinterpret_cast<const __nv_bfloat16*>(sm + buf * BUF_BYTES);
        const __nv_bfloat16* As_hi = base;
        const __nv_bfloat16* As_lo = base + TILE_HB;
        const __nv_bfloat16* Bs_hi = base + 2 * TILE_HB;
        const __nv_bfloat16* Bs_lo = base + 3 * TILE_HB;

#pragma unroll
        for (int kk = 0; kk < BK; kk += 16) {
            wmma::fragment<wmma::matrix_a, 16, 16, 16, __nv_bfloat16, wmma::row_major> ah[2], al[2];
#pragma unroll
            for (int i = 0; i < 2; i++) {
                wmma::load_matrix_sync(ah[i], As_hi + (warp_m + 16 * i) * LDT + kk, LDT);
                wmma::load_matrix_sync(al[i], As_lo + (warp_m + 16 * i) * LDT + kk, LDT);
            }
#pragma unroll
            for (int j = 0; j < 4; j++) {
                wmma::fragment<wmma::matrix_b, 16, 16, 16, __nv_bfloat16, wmma::col_major> bh, bl;
                wmma::load_matrix_sync(bh, Bs_hi + (warp_n + 16 * j) * LDT + kk, LDT);
                wmma::load_matrix_sync(bl, Bs_lo + (warp_n + 16 * j) * LDT + kk, LDT);
#pragma unroll
                for (int i = 0; i < 2; i++) {
                    wmma::mma_sync(acc[i][j], ah[i], bh, acc[i][j]);
                    wmma::mma_sync(acc[i][j], ah[i], bl, acc[i][j]);
                    wmma::mma_sync(acc[i][j], al[i], bh, acc[i][j]);
                }
            }
        }
        __syncthreads();
    }

    // epilogue: frags -> smem -> bias add -> global (float4)
    float* Cs = reinterpret_cast<float*>(sm);
#pragma unroll
    for (int i = 0; i < 2; i++)
#pragma unroll
        for (int j = 0; j < 4; j++)
            wmma::store_matrix_sync(Cs + (warp_m + 16 * i) * EPI_LD + warp_n + 16 * j,
                                    acc[i][j], EPI_LD, wmma::mem_row_major);
    __syncthreads();

#pragma unroll
    for (int it = 0; it < 16; it++) {
        int idx = tid + it * 256;          // 0..4095
        int row = idx >> 5;                // 0..127
        int c4 = (idx & 31) * 4;           // 0..124
        float4 v = *reinterpret_cast<const float4*>(&Cs[row * EPI_LD + c4]);
        const int col0 = ntile * 128 + c4;
        v.x += bias[col0 + 0];
        v.y += bias[col0 + 1];
        v.z += bias[col0 + 2];
        v.w += bias[col0 + 3];
        *reinterpret_cast<float4*>(&C[(size_t)(mtile * 128 + row) * N + col0]) = v;
    }
}

// ---------------------------------------------------------------------------
// MQA flash attention v2 (verified in round 2)
// ---------------------------------------------------------------------------
#define AT_BK 128
#define QS_STR 132

__global__ __launch_bounds__(256, 1) void mqa_attn_v2(
    const float* __restrict__ qkv, float* __restrict__ out)
{
    extern __shared__ float smf[];
    float* Qs  = smf;
    float* KPs = smf + 128 * QS_STR;
    float* Vs  = KPs + 128 * QS_STR;

    const int tid = threadIdx.x;
    const int tx = tid & 15;
    const int ty = tid >> 4;
    const int b = blockIdx.y;
    const int q0 = blockIdx.x * 8;
    const float scale = 0.08838834764831845f;

#pragma unroll
    for (int it = 0; it < 16; ++it) {
        int idx = tid + it * 256;
        int r = idx & 127;
        int c = idx >> 7;
        int h = r >> 3, qi = r & 7;
        float4 v = *reinterpret_cast<const float4*>(
            &qkv[(size_t)(b * SS + q0 + qi) * NQKV + h * HDIM + 4 * c]);
        Qs[(4 * c + 0) * QS_STR + r] = v.x * scale;
        Qs[(4 * c + 1) * QS_STR + r] = v.y * scale;
        Qs[(4 * c + 2) * QS_STR + r] = v.z * scale;
        Qs[(4 * c + 3) * QS_STR + r] = v.w * scale;
    }

    float m[8], l[8], O[8][8];
#pragma unroll
    for (int i = 0; i < 8; i++) {
        m[i] = -INFINITY; l[i] = 0.0f;
#pragma unroll
        for (int j = 0; j < 8; j++) O[i][j] = 0.0f;
    }

    const int q_max = q0 + 7;
    const int ntiles = q_max / AT_BK + 1;

    for (int t = 0; t < ntiles; ++t) {
        const int t0 = t * AT_BK;
        __syncthreads();

#pragma unroll
        for (int it = 0; it < 16; ++it) {
            int idx = tid + it * 256;
            int k = idx & 127;
            int c = idx >> 7;
            float4 v = *reinterpret_cast<const float4*>(
                &qkv[(size_t)(b * SS + t0 + k) * NQKV + HH * HDIM + 4 * c]);
            KPs[(4 * c + 0) * QS_STR + k] = v.x;
            KPs[(4 * c + 1) * QS_STR + k] = v.y;
            KPs[(4 * c + 2) * QS_STR + k] = v.z;
            KPs[(4 * c + 3) * QS_STR + k] = v.w;
        }
#pragma unroll
        for (int it = 0; it < 16; ++it) {
            int idx = tid + it * 256;
            int k = idx >> 5;
            int c = idx & 31;
            float4 v = *reinterpret_cast<const float4*>(
                &qkv[(size_t)(b * SS + t0 + k) * NQKV + HH * HDIM + HDIM + 4 * c]);
            *reinterpret_cast<float4*>(&Vs[k * QS_STR + 4 * c]) = v;
        }
        __syncthreads();

        float s[8][8];
#pragma unroll
        for (int i = 0; i < 8; i++)
#pragma unroll
            for (int j = 0; j < 8; j++) s[i][j] = 0.0f;

#pragma unroll 4
        for (int d = 0; d < 128; ++d) {
            float a[8], bfr[8];
            float4 a0 = *reinterpret_cast<const float4*>(&Qs[d * QS_STR + ty * 8]);
            float4 a1 = *reinterpret_cast<const float4*>(&Qs[d * QS_STR + ty * 8 + 4]);
            a[0] = a0.x; a[1] = a0.y; a[2] = a0.z; a[3] = a0.w;
            a[4] = a1.x; a[5] = a1.y; a[6] = a1.z; a[7] = a1.w;
#pragma unroll
            for (int j = 0; j < 8; j++) bfr[j] = KPs[d * QS_STR + tx + 16 * j];
#pragma unroll
            for (int i = 0; i < 8; i++)
#pragma unroll
                for (int j = 0; j < 8; j++)
                    s[i][j] = fmaf(a[i], bfr[j], s[i][j]);
        }

        if (t == ntiles - 1) {
#pragma unroll
            for (int i = 0; i < 8; i++)
#pragma unroll
                for (int j = 0; j < 8; j++)
                    if (t0 + tx + 16 * j > q0 + i) s[i][j] = -1.0e30f;
        }

        float corr[8];
#pragma unroll
        for (int i = 0; i < 8; i++) {
            float mx = s[i][0];
#pragma unroll
            for (int j = 1; j < 8; j++) mx = fmaxf(mx, s[i][j]);
            mx = fmaxf(mx, __shfl_xor_sync(0xffffffffu, mx, 1));
            mx = fmaxf(mx, __shfl_xor_sync(0xffffffffu, mx, 2));
            mx = fmaxf(mx, __shfl_xor_sync(0xffffffffu, mx, 4));
            mx = fmaxf(mx, __shfl_xor_sync(0xffffffffu, mx, 8));
            float m_new = fmaxf(m[i], mx);
            corr[i] = __expf(m[i] - m_new);
            m[i] = m_new;
            float sum = 0.0f;
#pragma unroll
            for (int j = 0; j < 8; j++) {
                float p = __expf(s[i][j] - m_new);
                s[i][j] = p;
                sum += p;
            }
            sum += __shfl_xor_sync(0xffffffffu, sum, 1);
            sum += __shfl_xor_sync(0xffffffffu, sum, 2);
            sum += __shfl_xor_sync(0xffffffffu, sum, 4);
            sum += __shfl_xor_sync(0xffffffffu, sum, 8);
            l[i] = l[i] * corr[i] + sum;
#pragma unroll
            for (int j = 0; j < 8; j++) O[i][j] *= corr[i];
        }

        __syncthreads();
#pragma unroll
        for (int i = 0; i < 8; i++)
#pragma unroll
            for (int j = 0; j < 8; j++)
                KPs[(ty * 8 + i) * 128 + tx + 16 * j] = s[i][j];
        __syncthreads();

#pragma unroll 4
        for (int k = 0; k < 128; ++k) {
            float a[8], bfr[8];
#pragma unroll
            for (int i = 0; i < 8; i++) a[i] = KPs[(ty * 8 + i) * 128 + k];
#pragma unroll
            for (int j = 0; j < 8; j++) bfr[j] = Vs[k * QS_STR + tx + 16 * j];
#pragma unroll
            for (int i = 0; i < 8; i++)
#pragma unroll
                for (int j = 0; j < 8; j++)
                    O[i][j] = fmaf(a[i], bfr[j], O[i][j]);
        }
    }

#pragma unroll
    for (int i = 0; i < 8; i++) {
        float inv = 1.0f / l[i];
        size_t base = (size_t)(b * SS + q0 + i) * DD + ty * HDIM + tx;
#pragma unroll
        for (int j = 0; j < 8; j++)
            out[base + 16 * j] = O[i][j] * inv;
    }
}

// ---------------------------------------------------------------------------
extern "C" void kernel_launch(void* const* d_in, const int* in_sizes, int n_in,
                              void* d_out, int out_size)
{
    const float* hidden = (const float*)d_in[0];
    const float* W_attn = (const float*)d_in[1];
    const float* b_attn = (const float*)d_in[2];
    const float* W_proj = (const float*)d_in[3];
    const float* b_proj = (const float*)d_in[4];
    float* out = (float*)d_out;

    float *qkv, *att;
    __nv_bfloat16 *Xhi, *Xlo, *WaThi, *WaTlo, *WpThi, *WpTlo, *AThi, *ATlo;
    cudaGetSymbolAddress((void**)&qkv, g_qkv);
    cudaGetSymbolAddress((void**)&att, g_att);
    cudaGetSymbolAddress((void**)&Xhi, g_Xhi);
    cudaGetSymbolAddress((void**)&Xlo, g_Xlo);
    cudaGetSymbolAddress((void**)&WaThi, g_WaThi);
    cudaGetSymbolAddress((void**)&WaTlo, g_WaTlo);
    cudaGetSymbolAddress((void**)&WpThi, g_WpThi);
    cudaGetSymbolAddress((void**)&WpTlo, g_WpTlo);
    cudaGetSymbolAddress((void**)&AThi, g_AThi);
    cudaGetSymbolAddress((void**)&ATlo, g_ATlo);

    const int attn_smem = 128 * QS_STR * 3 * sizeof(float);       // 202,752 B
    const int gemm_smem = 2 * BUF_BYTES;                          // 81,920 B
    cudaFuncSetAttribute(mqa_attn_v2,
                         cudaFuncAttributeMaxDynamicSharedMemorySize, attn_smem);
    cudaFuncSetAttribute(wmma_gemm_bias,
                         cudaFuncAttributeMaxDynamicSharedMemorySize, gemm_smem);

    // 0) precision splits + weight transposes
    split_kernel<<<MM * DD / 1024, 256>>>(hidden, Xhi, Xlo, MM * DD);
    {
        dim3 g(NQKV / 32, DD / 32), blk(32, 8);
        split_transpose_kernel<<<g, blk>>>(W_attn, WaThi, WaTlo, DD, NQKV);
    }
    {
        dim3 g(DD / 32, DD / 32), blk(32, 8);
        split_transpose_kernel<<<g, blk>>>(W_proj, WpThi, WpTlo, DD, DD);
    }

    // 1) QKV GEMM (wmma tensor cores): [4096,2048] @ [2048,2304] + b_attn
    {
        dim3 grid(NQKV / 128, MM / 128);
        wmma_gemm_bias<<<grid, 256, gemm_smem>>>(Xhi, Xlo, WaThi, WaTlo,
                                                 b_attn, qkv, MM, NQKV, DD);
    }

    // 2) MQA causal flash attention
    {
        dim3 grid(SS / 8, BB);
        mqa_attn_v2<<<grid, 256, attn_smem>>>(qkv, att);
    }

    // 2b) split attention output for proj GEMM
    split_kernel<<<MM * DD / 1024, 256>>>(att, AThi, ATlo, MM * DD);

    // 3) Projection GEMM (wmma tensor cores): [4096,2048] @ [2048,2048] + b_proj
    {
        dim3 grid(DD / 128, MM / 128);
        wmma_gemm_bias<<<grid, 256, gemm_smem>>>(AThi, ATlo, WpThi, WpTlo,
                                                 b_proj, out, MM, DD, DD);
    }
}

// round 5
// speedup vs baseline: 3.5605x; 1.2746x over previous
#include <cuda_runtime.h>
#include <cuda_bf16.h>
#include <mma.h>
#include <math.h>
#include <cstdint>

using namespace nvcuda;

// Problem constants (GPTBigCode MQA)
#define BB 2
#define SS 2048
#define DD 2048
#define HH 16
#define HDIM 128
#define NQKV (HH * HDIM + 2 * HDIM)   // 2304
#define MM (BB * SS)                  // 4096

// ---------------- scratch (device globals; no allocation allowed) ----------
__device__ float g_qkv[MM * NQKV];                    // [4096, 2304]
__device__ float g_att[MM * DD];                      // [4096, 2048]
__device__ __nv_bfloat16 g_Xhi[MM * DD];
__device__ __nv_bfloat16 g_Xlo[MM * DD];
__device__ __nv_bfloat16 g_WaThi[NQKV * DD];
__device__ __nv_bfloat16 g_WaTlo[NQKV * DD];
__device__ __nv_bfloat16 g_WpThi[DD * DD];
__device__ __nv_bfloat16 g_WpTlo[DD * DD];
__device__ __nv_bfloat16 g_AThi[MM * DD];
__device__ __nv_bfloat16 g_ATlo[MM * DD];

// ---------------- helpers ---------------------------------------------------
__device__ __forceinline__ uint32_t smem_u32(const void* p) {
    uint32_t a;
    asm("{ .reg .u64 t; cvta.to.shared.u64 t, %1; cvt.u32.u64 %0, t; }" : "=r"(a) : "l"(p));
    return a;
}
__device__ __forceinline__ void cp_async16(uint32_t dst, const void* src) {
    asm volatile("cp.async.cg.shared.global [%0], [%1], 16;" :: "r"(dst), "l"(src));
}
__device__ __forceinline__ void cp_commit() {
    asm volatile("cp.async.commit_group;" ::: "memory");
}
template <int N>
__device__ __forceinline__ void cp_wait() {
    asm volatile("cp.async.wait_group %0;" :: "n"(N) : "memory");
}
// d = {hi:cvt(hi), lo:cvt(lo)}
__device__ __forceinline__ uint32_t pack_bf16(float lo, float hi) {
    uint32_t r;
    asm("cvt.rn.bf16x2.f32 %0, %1, %2;" : "=r"(r) : "f"(hi), "f"(lo));
    return r;
}
__device__ __forceinline__ void mma_bf16(float* c, const uint32_t* a,
                                         uint32_t b0, uint32_t b1) {
    asm volatile("mma.sync.aligned.m16n8k16.row.col.f32.bf16.bf16.f32 "
        "{%0,%1,%2,%3}, {%4,%5,%6,%7}, {%8,%9}, {%0,%1,%2,%3};"
        : "+f"(c[0]), "+f"(c[1]), "+f"(c[2]), "+f"(c[3])
        : "r"(a[0]), "r"(a[1]), "r"(a[2]), "r"(a[3]), "r"(b0), "r"(b1));
}
__device__ __forceinline__ void splitf(float v, __nv_bfloat16& h, __nv_bfloat16& l) {
    h = __float2bfloat16(v);
    l = __float2bfloat16(v - __bfloat162float(h));
}

// ---------------------------------------------------------------------------
// split: fp32 -> (bf16 hi, bf16 lo), flat
// ---------------------------------------------------------------------------
__global__ __launch_bounds__(256) void split_kernel(
    const float* __restrict__ X, __nv_bfloat16* __restrict__ hi,
    __nv_bfloat16* __restrict__ lo, int n)
{
    int i = (blockIdx.x * 256 + threadIdx.x) * 4;
    if (i >= n) return;
    float4 v = *reinterpret_cast<const float4*>(&X[i]);
    __nv_bfloat16 h0, h1, h2, h3, l0, l1, l2, l3;
    splitf(v.x, h0, l0); splitf(v.y, h1, l1);
    splitf(v.z, h2, l2); splitf(v.w, h3, l3);
    __nv_bfloat162 hp0 = {h0, h1}, hp1 = {h2, h3}, lp0 = {l0, l1}, lp1 = {l2, l3};
    *reinterpret_cast<__nv_bfloat162*>(&hi[i]) = hp0;
    *reinterpret_cast<__nv_bfloat162*>(&hi[i + 2]) = hp1;
    *reinterpret_cast<__nv_bfloat162*>(&lo[i]) = lp0;
    *reinterpret_cast<__nv_bfloat162*>(&lo[i + 2]) = lp1;
}

// ---------------------------------------------------------------------------
// split + transpose: W[K,N] fp32 -> T{hi,lo}[N,K] bf16
// ---------------------------------------------------------------------------
__global__ __launch_bounds__(256) void split_transpose_kernel(
    const float* __restrict__ W, __nv_bfloat16* __restrict__ Thi,
    __nv_bfloat16* __restrict__ Tlo, int K, int N)
{
    __shared__ float t[32][33];
    int tx = threadIdx.x, ty = threadIdx.y;
    int n0 = blockIdx.x * 32, k0 = blockIdx.y * 32;
#pragma unroll
    for (int i = 0; i < 4; i++)
        t[ty + 8 * i][tx] = W[(size_t)(k0 + ty + 8 * i) * N + n0 + tx];
    __syncthreads();
#pragma unroll
    for (int i = 0; i < 4; i++) {
        float v = t[tx][ty + 8 * i];
        __nv_bfloat16 h, l;
        splitf(v, h, l);
        size_t o = (size_t)(n0 + ty + 8 * i) * K + k0 + tx;
        Thi[o] = h;
        Tlo[o] = l;
    }
}

// ---------------------------------------------------------------------------
// wmma bf16 3-term split GEMM + bias (unchanged; verified round 4)
// ---------------------------------------------------------------------------
#define BK 32
#define LDT 40
#define TILE_HB (128 * LDT)
#define TILE_BYTES (TILE_HB * 2)
#define BUF_BYTES (4 * TILE_BYTES)
#define EPI_LD 136

__global__ __launch_bounds__(256, 1)
void wmma_gemm_bias(const __nv_bfloat16* __restrict__ Ahi,
                    const __nv_bfloat16* __restrict__ Alo,
                    const __nv_bfloat16* __restrict__ Bhi,
                    const __nv_bfloat16* __restrict__ Blo,
                    const float* __restrict__ bias, float* __restrict__ C,
                    int M, int N, int K)
{
    extern __shared__ char sm[];
    const uint32_t smb = smem_u32(sm);
    const int tid = threadIdx.x;
    const int wid = tid >> 5;
    const int ntile = blockIdx.x, mtile = blockIdx.y;

    const int warp_m = (wid >> 1) * 32;
    const int warp_n = (wid & 1) * 64;

    const __nv_bfloat16* srcs[4] = {
        Ahi + (size_t)mtile * 128 * K, Alo + (size_t)mtile * 128 * K,
        Bhi + (size_t)ntile * 128 * K, Blo + (size_t)ntile * 128 * K };

    auto issue_load = [&](int b, int k0) {
        const uint32_t bufb = smb + b * BUF_BYTES;
#pragma unroll
        for (int t = 0; t < 4; t++) {
            const __nv_bfloat16* s = srcs[t];
            const uint32_t tb = bufb + t * TILE_BYTES;
#pragma unroll
            for (int it = 0; it < 2; it++) {
                int idx = tid + it * 256;
                int row = idx >> 2;
                int ch = idx & 3;
                cp_async16(tb + (row * LDT + ch * 8) * 2,
                           s + (size_t)row * K + k0 + ch * 8);
            }
        }
        cp_commit();
    };

    wmma::fragment<wmma::accumulator, 16, 16, 16, float> acc[2][4];
#pragma unroll
    for (int i = 0; i < 2; i++)
#pragma unroll
        for (int j = 0; j < 4; j++) wmma::fill_fragment(acc[i][j], 0.0f);

    const int niter = K / BK;
    issue_load(0, 0);

    for (int iter = 0; iter < niter; iter++) {
        const int buf = iter & 1;
        if (iter + 1 < niter) {
            issue_load(buf ^ 1, (iter + 1) * BK);
            cp_wait<1>();
        } else {
            cp_wait<0>();
        }
        __syncthreads();

        const __nv_bfloat16* base = reinterpret_cast<const __nv_bfloat16*>(sm + buf * BUF_BYTES);
        const __nv_bfloat16* As_hi = base;
        const __nv_bfloat16* As_lo = base + TILE_HB;
        const __nv_bfloat16* Bs_hi = base + 2 * TILE_HB;
        const __nv_bfloat16* Bs_lo = base + 3 * TILE_HB;

#pragma unroll
        for (int kk = 0; kk < BK; kk += 16) {
            wmma::fragment<wmma::matrix_a, 16, 16, 16, __nv_bfloat16, wmma::row_major> ah[2], al[2];
#pragma unroll
            for (int i = 0; i < 2; i++) {
                wmma::load_matrix_sync(ah[i], As_hi + (warp_m + 16 * i) * LDT + kk, LDT);
                wmma::load_matrix_sync(al[i], As_lo + (warp_m + 16 * i) * LDT + kk, LDT);
            }
#pragma unroll
            for (int j = 0; j < 4; j++) {
                wmma::fragment<wmma::matrix_b, 16, 16, 16, __nv_bfloat16, wmma::col_major> bh, bl;
                wmma::load_matrix_sync(bh, Bs_hi + (warp_n + 16 * j) * LDT + kk, LDT);
                wmma::load_matrix_sync(bl, Bs_lo + (warp_n + 16 * j) * LDT + kk, LDT);
#pragma unroll
                for (int i = 0; i < 2; i++) {
                    wmma::mma_sync(acc[i][j], ah[i], bh, acc[i][j]);
                    wmma::mma_sync(acc[i][j], ah[i], bl, acc[i][j]);
                    wmma::mma_sync(acc[i][j], al[i], bh, acc[i][j]);
                }
            }
        }
        __syncthreads();
    }

    float* Cs = reinterpret_cast<float*>(sm);
#pragma unroll
    for (int i = 0; i < 2; i++)
#pragma unroll
        for (int j = 0; j < 4; j++)
            wmma::store_matrix_sync(Cs + (warp_m + 16 * i) * EPI_LD + warp_n + 16 * j,
                                    acc[i][j], EPI_LD, wmma::mem_row_major);
    __syncthreads();

#pragma unroll
    for (int it = 0; it < 16; it++) {
        int idx = tid + it * 256;
        int row = idx >> 5;
        int c4 = (idx & 31) * 4;
        float4 v = *reinterpret_cast<const float4*>(&Cs[row * EPI_LD + c4]);
        const int col0 = ntile * 128 + c4;
        v.x += bias[col0 + 0];
        v.y += bias[col0 + 1];
        v.z += bias[col0 + 2];
        v.w += bias[col0 + 3];
        *reinterpret_cast<float4*>(&C[(size_t)(mtile * 128 + row) * N + col0]) = v;
    }
}

// ---------------------------------------------------------------------------
// MQA flash attention v3 — tensor cores via mma.sync m16n8k16 bf16 (3-term).
//
// Block: 256 thr (8 warps), 128 score rows = 16 heads x 8 q rows, key tiles
// of 128. Warp w owns rows 16w..16w+15 (heads 2w, 2w+1) for ALL keys -> the
// full softmax of those rows is warp-local (4-lane shfl groups).
//
// m16n8k16 accumulator mapping (architectural): thread lane: g=lane>>2,
// t=lane&3; c0,c1 = rows g, cols 2t,2t+1; c2,c3 = row g+8 same cols.
// QK accum (16x128 per warp, 16 n-frags) -> softmax in-register ->
// P repacked as A-fragments -> PV accum O (16x128 per warp).
//
// smem (dyn, 204 KB): Qhi/Qlo [row][136], Khi/Klo [key][136],
// Vthi/Vtlo [dim][136] (V transposed). grid = (S/8, B).
// ---------------------------------------------------------------------------
#define ALD 136                       // smem ld in halves
#define ATILE (128 * ALD)             // halves per array

__global__ __launch_bounds__(256, 1) void mqa_attn_v3(
    const float* __restrict__ qkv, float* __restrict__ out)
{
    extern __shared__ __nv_bfloat16 smh[];
    __nv_bfloat16* Qhi = smh;
    __nv_bfloat16* Qlo = smh + ATILE;
    __nv_bfloat16* Khi = smh + 2 * ATILE;
    __nv_bfloat16* Klo = smh + 3 * ATILE;
    __nv_bfloat16* Vthi = smh + 4 * ATILE;
    __nv_bfloat16* Vtlo = smh + 5 * ATILE;

    const int tid = threadIdx.x;
    const int w = tid >> 5;
    const int lane = tid & 31;
    const int g = lane >> 2;          // 0..7
    const int t = lane & 3;           // 0..3
    const int b = blockIdx.y;
    const int q0 = blockIdx.x * 8;
    const float scale = 0.08838834764831845f;

    const int r_lo = w * 16 + g;      // head 2w, qi = g
    // r_hi = r_lo + 8                // head 2w+1, qi = g

    // ---- load Q (128 rows x 128 d), scale + split into smem ----
#pragma unroll
    for (int it = 0; it < 16; ++it) {
        int idx = tid + it * 256;
        int row = idx >> 5;           // 0..127  (h = row>>3, qi = row&7)
        int c4 = (idx & 31) * 4;
        float4 v = *reinterpret_cast<const float4*>(
            &qkv[(size_t)(b * SS + q0 + (row & 7)) * NQKV + (row >> 3) * HDIM + c4]);
        __nv_bfloat16 h0, h1, h2, h3, l0, l1, l2, l3;
        splitf(v.x * scale, h0, l0); splitf(v.y * scale, h1, l1);
        splitf(v.z * scale, h2, l2); splitf(v.w * scale, h3, l3);
        __nv_bfloat162 a0 = {h0, h1}, a1 = {h2, h3};
        __nv_bfloat162 b0 = {l0, l1}, b1 = {l2, l3};
        *reinterpret_cast<__nv_bfloat162*>(&Qhi[row * ALD + c4]) = a0;
        *reinterpret_cast<__nv_bfloat162*>(&Qhi[row * ALD + c4 + 2]) = a1;
        *reinterpret_cast<__nv_bfloat162*>(&Qlo[row * ALD + c4]) = b0;
        *reinterpret_cast<__nv_bfloat162*>(&Qlo[row * ALD + c4 + 2]) = b1;
    }

    // flash state: rows r_lo (m0,l0) and r_lo+8 (m1,l1)
    float m0 = -INFINITY, m1 = -INFINITY, l0s = 0.0f, l1s = 0.0f;
    float O[16][4];
#pragma unroll
    for (int j = 0; j < 16; j++)
#pragma unroll
        for (int c = 0; c < 4; c++) O[j][c] = 0.0f;

    const int ntiles = (q0 + 7) / 128 + 1;

    for (int tt = 0; tt < ntiles; ++tt) {
        const int t0 = tt * 128;
        __syncthreads();

        // ---- load K tile -> Khi/Klo [key][d] ----
#pragma unroll
        for (int it = 0; it < 16; ++it) {
            int idx = tid + it * 256;
            int row = idx >> 5;       // key
            int c4 = (idx & 31) * 4;
            float4 v = *reinterpret_cast<const float4*>(
                &qkv[(size_t)(b * SS + t0 + row) * NQKV + HH * HDIM + c4]);
            __nv_bfloat16 h0, h1, h2, h3, l0, l1, l2, l3;
            splitf(v.x, h0, l0); splitf(v.y, h1, l1);
            splitf(v.z, h2, l2); splitf(v.w, h3, l3);
            __nv_bfloat162 a0 = {h0, h1}, a1 = {h2, h3};
            __nv_bfloat162 b0 = {l0, l1}, b1 = {l2, l3};
            *reinterpret_cast<__nv_bfloat162*>(&Khi[row * ALD + c4]) = a0;
            *reinterpret_cast<__nv_bfloat162*>(&Khi[row * ALD + c4 + 2]) = a1;
            *reinterpret_cast<__nv_bfloat162*>(&Klo[row * ALD + c4]) = b0;
            *reinterpret_cast<__nv_bfloat162*>(&Klo[row * ALD + c4 + 2]) = b1;
        }
        // ---- load V tile transposed -> Vthi/Vtlo [dim][key] ----
#pragma unroll
        for (int it = 0; it < 16; ++it) {
            int idx = tid + it * 256;
            int row = idx >> 5;       // key
            int c4 = (idx & 31) * 4;  // dim base
            float4 v = *reinterpret_cast<const float4*>(
                &qkv[(size_t)(b * SS + t0 + row) * NQKV + HH * HDIM + HDIM + c4]);
            __nv_bfloat16 h, l;
            splitf(v.x, h, l); Vthi[(c4 + 0) * ALD + row] = h; Vtlo[(c4 + 0) * ALD + row] = l;
            splitf(v.y, h, l); Vthi[(c4 + 1) * ALD + row] = h; Vtlo[(c4 + 1) * ALD + row] = l;
            splitf(v.z, h, l); Vthi[(c4 + 2) * ALD + row] = h; Vtlo[(c4 + 2) * ALD + row] = l;
            splitf(v.w, h, l); Vthi[(c4 + 3) * ALD + row] = h; Vtlo[(c4 + 3) * ALD + row] = l;
        }
        __syncthreads();

        // ---- QK^T: S (16 rows x 128 keys per warp) ----
        float s[16][4];
#pragma unroll
        for (int j = 0; j < 16; j++)
#pragma unroll
            for (int c = 0; c < 4; c++) s[j][c] = 0.0f;

#pragma unroll
        for (int k = 0; k < 8; ++k) {    // k-step: dims 16k..16k+15
            uint32_t ah[4], al[4];
            const int d0 = 16 * k + 2 * t;
            ah[0] = *reinterpret_cast<const uint32_t*>(&Qhi[r_lo * ALD + d0]);
            ah[1] = *reinterpret_cast<const uint32_t*>(&Qhi[(r_lo + 8) * ALD + d0]);
            ah[2] = *reinterpret_cast<const uint32_t*>(&Qhi[r_lo * ALD + d0 + 8]);
            ah[3] = *reinterpret_cast<const uint32_t*>(&Qhi[(r_lo + 8) * ALD + d0 + 8]);
            al[0] = *reinterpret_cast<const uint32_t*>(&Qlo[r_lo * ALD + d0]);
            al[1] = *reinterpret_cast<const uint32_t*>(&Qlo[(r_lo + 8) * ALD + d0]);
            al[2] = *reinterpret_cast<const uint32_t*>(&Qlo[r_lo * ALD + d0 + 8]);
            al[3] = *reinterpret_cast<const uint32_t*>(&Qlo[(r_lo + 8) * ALD + d0 + 8]);
#pragma unroll
            for (int j = 0; j < 16; ++j) {   // n-frag: keys 8j..8j+7
                const int kr = (8 * j + g) * ALD + d0;
                uint32_t bh0 = *reinterpret_cast<const uint32_t*>(&Khi[kr]);
                uint32_t bh1 = *reinterpret_cast<const uint32_t*>(&Khi[kr + 8]);
                uint32_t bl0 = *reinterpret_cast<const uint32_t*>(&Klo[kr]);
                uint32_t bl1 = *reinterpret_cast<const uint32_t*>(&Klo[kr + 8]);
                mma_bf16(s[j], ah, bh0, bh1);
                mma_bf16(s[j], ah, bl0, bl1);
                mma_bf16(s[j], al, bh0, bh1);
            }
        }

        // ---- causal mask (last tile only). col = t0+8j+2t+u, row qi = g ----
        if (tt == ntiles - 1) {
#pragma unroll
            for (int j = 0; j < 16; ++j) {
                const int col = t0 + 8 * j + 2 * t;
                if (col > q0 + g)     { s[j][0] = -1e30f; s[j][2] = -1e30f; }
                if (col + 1 > q0 + g) { s[j][1] = -1e30f; s[j][3] = -1e30f; }
            }
        }

        // ---- online softmax (rows r_lo and r_lo+8) ----
        float mx0 = -INFINITY, mx1 = -INFINITY;
#pragma unroll
        for (int j = 0; j < 16; ++j) {
            mx0 = fmaxf(mx0, fmaxf(s[j][0], s[j][1]));
            mx1 = fmaxf(mx1, fmaxf(s[j][2], s[j][3]));
        }
        mx0 = fmaxf(mx0, __shfl_xor_sync(0xffffffffu, mx0, 1));
        mx0 = fmaxf(mx0, __shfl_xor_sync(0xffffffffu, mx0, 2));
        mx1 = fmaxf(mx1, __shfl_xor_sync(0xffffffffu, mx1, 1));
        mx1 = fmaxf(mx1, __shfl_xor_sync(0xffffffffu, mx1, 2));
        const float mn0 = fmaxf(m0, mx0), mn1 = fmaxf(m1, mx1);
        const float corr0 = __expf(m0 - mn0), corr1 = __expf(m1 - mn1);
        m0 = mn0; m1 = mn1;

        float sum0 = 0.0f, sum1 = 0.0f;
#pragma unroll
        for (int j = 0; j < 16; ++j) {
            s[j][0] = __expf(s[j][0] - mn0);
            s[j][1] = __expf(s[j][1] - mn0);
            s[j][2] = __expf(s[j][2] - mn1);
            s[j][3] = __expf(s[j][3] - mn1);
            sum0 += s[j][0] + s[j][1];
            sum1 += s[j][2] + s[j][3];
        }
        sum0 += __shfl_xor_sync(0xffffffffu, sum0, 1);
        sum0 += __shfl_xor_sync(0xffffffffu, sum0, 2);
        sum1 += __shfl_xor_sync(0xffffffffu, sum1, 1);
        sum1 += __shfl_xor_sync(0xffffffffu, sum1, 2);
        l0s = l0s * corr0 + sum0;
        l1s = l1s * corr1 + sum1;

#pragma unroll
        for (int j = 0; j < 16; ++j) {
            O[j][0] *= corr0; O[j][1] *= corr0;
            O[j][2] *= corr1; O[j][3] *= corr1;
        }

        // ---- repack P (f32 accum) -> bf16 hi/lo A-fragments ----
        uint32_t pah[8][4], pal[8][4];
#pragma unroll
        for (int ss = 0; ss < 8; ++ss) {
            float v00 = s[2 * ss][0], v01 = s[2 * ss][1];
            float v10 = s[2 * ss][2], v11 = s[2 * ss][3];
            float v20 = s[2 * ss + 1][0], v21 = s[2 * ss + 1][1];
            float v30 = s[2 * ss + 1][2], v31 = s[2 * ss + 1][3];
            __nv_bfloat16 h, l;
            float h00, h01, h10, h11, h20, h21, h30, h31;
            splitf(v00, h, l); h00 = __bfloat162float(h); float q00 = __bfloat162float(l);
            splitf(v01, h, l); h01 = __bfloat162float(h); float q01 = __bfloat162float(l);
            splitf(v10, h, l); h10 = __bfloat162float(h); float q10 = __bfloat162float(l);
            splitf(v11, h, l); h11 = __bfloat162float(h); float q11 = __bfloat162float(l);
            splitf(v20, h, l); h20 = __bfloat162float(h); float q20 = __bfloat162float(l);
            splitf(v21, h, l); h21 = __bfloat162float(h); float q21 = __bfloat162float(l);
            splitf(v30, h, l); h30 = __bfloat162float(h); float q30 = __bfloat162float(l);
            splitf(v31, h, l); h31 = __bfloat162float(h); float q31 = __bfloat162float(l);
            pah[ss][0] = pack_bf16(h00, h01); pal[ss][0] = pack_bf16(q00, q01);
            pah[ss][1] = pack_bf16(h10, h11); pal[ss][1] = pack_bf16(q10, q11);
            pah[ss][2] = pack_bf16(h20, h21); pal[ss][2] = pack_bf16(q20, q21);
            pah[ss][3] = pack_bf16(h30, h31); pal[ss][3] = pack_bf16(q30, q31);
        }

        // ---- PV: O += P @ V   (k = keys, n = dims) ----
#pragma unroll
        for (int ss = 0; ss < 8; ++ss) {     // keys 16ss..16ss+15
            const int kb = 16 * ss + 2 * t;
#pragma unroll
            for (int j2 = 0; j2 < 16; ++j2) {  // dims 8j2..8j2+7
                const int vr = (8 * j2 + g) * ALD + kb;
                uint32_t bh0 = *reinterpret_cast<const uint32_t*>(&Vthi[vr]);
                uint32_t bh1 = *reinterpret_cast<const uint32_t*>(&Vthi[vr + 8]);
                uint32_t bl0 = *reinterpret_cast<const uint32_t*>(&Vtlo[vr]);
                uint32_t bl1 = *reinterpret_cast<const uint32_t*>(&Vtlo[vr + 8]);
                mma_bf16(O[j2], pah[ss], bh0, bh1);
                mma_bf16(O[j2], pah[ss], bl0, bl1);
                mma_bf16(O[j2], pal[ss], bh0, bh1);
            }
        }
    }

    // ---- epilogue: normalize + store ----
    const float inv0 = 1.0f / l0s, inv1 = 1.0f / l1s;
    const size_t row0 = (size_t)(b * SS + q0 + g) * DD;   // qi = g for both
    const int h_lo = 2 * w, h_hi = 2 * w + 1;
#pragma unroll
    for (int j2 = 0; j2 < 16; ++j2) {
        const int d = 8 * j2 + 2 * t;
        float2 v0 = {O[j2][0] * inv0, O[j2][1] * inv0};
        float2 v1 = {O[j2][2] * inv1, O[j2][3] * inv1};
        *reinterpret_cast<float2*>(&out[row0 + h_lo * HDIM + d]) = v0;
        *reinterpret_cast<float2*>(&out[row0 + h_hi * HDIM + d]) = v1;
    }
}

// ---------------------------------------------------------------------------
extern "C" void kernel_launch(void* const* d_in, const int* in_sizes, int n_in,
                              void* d_out, int out_size)
{
    const float* hidden = (const float*)d_in[0];
    const float* W_attn = (const float*)d_in[1];
    const float* b_attn = (const float*)d_in[2];
    const float* W_proj = (const float*)d_in[3];
    const float* b_proj = (const float*)d_in[4];
    float* out = (float*)d_out;

    float *qkv, *att;
    __nv_bfloat16 *Xhi, *Xlo, *WaThi, *WaTlo, *WpThi, *WpTlo, *AThi, *ATlo;
    cudaGetSymbolAddress((void**)&qkv, g_qkv);
    cudaGetSymbolAddress((void**)&att, g_att);
    cudaGetSymbolAddress((void**)&Xhi, g_Xhi);
    cudaGetSymbolAddress((void**)&Xlo, g_Xlo);
    cudaGetSymbolAddress((void**)&WaThi, g_WaThi);
    cudaGetSymbolAddress((void**)&WaTlo, g_WaTlo);
    cudaGetSymbolAddress((void**)&WpThi, g_WpThi);
    cudaGetSymbolAddress((void**)&WpTlo, g_WpTlo);
    cudaGetSymbolAddress((void**)&AThi, g_AThi);
    cudaGetSymbolAddress((void**)&ATlo, g_ATlo);

    const int attn_smem = 6 * ATILE * sizeof(__nv_bfloat16);      // 208,896 B
    const int gemm_smem = 2 * BUF_BYTES;                          // 81,920 B
    cudaFuncSetAttribute(mqa_attn_v3,
                         cudaFuncAttributeMaxDynamicSharedMemorySize, attn_smem);
    cudaFuncSetAttribute(wmma_gemm_bias,
                         cudaFuncAttributeMaxDynamicSharedMemorySize, gemm_smem);

    // 0) precision splits + weight transposes
    split_kernel<<<MM * DD / 1024, 256>>>(hidden, Xhi, Xlo, MM * DD);
    {
        dim3 g(NQKV / 32, DD / 32), blk(32, 8);
        split_transpose_kernel<<<g, blk>>>(W_attn, WaThi, WaTlo, DD, NQKV);
    }
    {
        dim3 g(DD / 32, DD / 32), blk(32, 8);
        split_transpose_kernel<<<g, blk>>>(W_proj, WpThi, WpTlo, DD, DD);
    }

    // 1) QKV GEMM (tensor cores)
    {
        dim3 grid(NQKV / 128, MM / 128);
        wmma_gemm_bias<<<grid, 256, gemm_smem>>>(Xhi, Xlo, WaThi, WaTlo,
                                                 b_attn, qkv, MM, NQKV, DD);
    }

    // 2) MQA causal flash attention (tensor cores)
    {
        dim3 grid(SS / 8, BB);
        mqa_attn_v3<<<grid, 256, attn_smem>>>(qkv, att);
    }

    // 2b) split attention output for proj GEMM
    split_kernel<<<MM * DD / 1024, 256>>>(att, AThi, ATlo, MM * DD);

    // 3) Projection GEMM (tensor cores)
    {
        dim3 grid(DD / 128, MM / 128);
        wmma_gemm_bias<<<grid, 256, gemm_smem>>>(AThi, ATlo, WpThi, WpTlo,
                                                 b_proj, out, MM, DD, DD);
    }
}

// round 6
// speedup vs baseline: 5.1094x; 1.4350x over previous
#include <cuda_runtime.h>
#include <cuda_bf16.h>
#include <mma.h>
#include <math.h>
#include <cstdint>

using namespace nvcuda;

// Problem constants (GPTBigCode MQA)
#define BB 2
#define SS 2048
#define DD 2048
#define HH 16
#define HDIM 128
#define NQKV (HH * HDIM + 2 * HDIM)   // 2304
#define MM (BB * SS)                  // 4096

// ---------------- scratch (device globals; no allocation allowed) ----------
__device__ __nv_bfloat16 g_qkvhi[MM * NQKV];          // QKV out split [M,2304]
__device__ __nv_bfloat16 g_qkvlo[MM * NQKV];
__device__ __nv_bfloat16 g_Xhi[MM * DD];              // hidden split [M,K]
__device__ __nv_bfloat16 g_Xlo[MM * DD];
__device__ __nv_bfloat16 g_WaThi[NQKV * DD];          // W_attn^T split [N,K]
__device__ __nv_bfloat16 g_WaTlo[NQKV * DD];
__device__ __nv_bfloat16 g_WpThi[DD * DD];            // W_proj^T split [N,K]
__device__ __nv_bfloat16 g_WpTlo[DD * DD];
__device__ __nv_bfloat16 g_AThi[MM * DD];             // attention out split [M,K]
__device__ __nv_bfloat16 g_ATlo[MM * DD];
__device__ __nv_bfloat16 g_Vthi[BB * HDIM * SS];      // V transposed [B][d][s]
__device__ __nv_bfloat16 g_Vtlo[BB * HDIM * SS];

// ---------------- helpers ---------------------------------------------------
__device__ __forceinline__ uint32_t smem_u32(const void* p) {
    uint32_t a;
    asm("{ .reg .u64 t; cvta.to.shared.u64 t, %1; cvt.u32.u64 %0, t; }" : "=r"(a) : "l"(p));
    return a;
}
__device__ __forceinline__ void cp_async16(uint32_t dst, const void* src) {
    asm volatile("cp.async.cg.shared.global [%0], [%1], 16;" :: "r"(dst), "l"(src));
}
__device__ __forceinline__ void cp_commit() {
    asm volatile("cp.async.commit_group;" ::: "memory");
}
template <int N>
__device__ __forceinline__ void cp_wait() {
    asm volatile("cp.async.wait_group %0;" :: "n"(N) : "memory");
}
__device__ __forceinline__ void mma_bf16(float* c, const uint32_t* a,
                                         uint32_t b0, uint32_t b1) {
    asm volatile("mma.sync.aligned.m16n8k16.row.col.f32.bf16.bf16.f32 "
        "{%0,%1,%2,%3}, {%4,%5,%6,%7}, {%8,%9}, {%0,%1,%2,%3};"
        : "+f"(c[0]), "+f"(c[1]), "+f"(c[2]), "+f"(c[3])
        : "r"(a[0]), "r"(a[1]), "r"(a[2]), "r"(a[3]), "r"(b0), "r"(b1));
}
__device__ __forceinline__ void splitf(float v, __nv_bfloat16& h, __nv_bfloat16& l) {
    h = __float2bfloat16(v);
    l = __float2bfloat16(v - __bfloat162float(h));
}
__device__ __forceinline__ uint32_t pack2(float a, float b) {   // a->low, b->high
    uint32_t r;
    asm("cvt.rn.bf16x2.f32 %0, %1, %2;" : "=r"(r) : "f"(b), "f"(a));
    return r;
}

// ---------------------------------------------------------------------------
// split: fp32 -> (bf16 hi, bf16 lo), flat
// ---------------------------------------------------------------------------
__global__ __launch_bounds__(256) void split_kernel(
    const float* __restrict__ X, __nv_bfloat16* __restrict__ hi,
    __nv_bfloat16* __restrict__ lo, int n)
{
    int i = (blockIdx.x * 256 + threadIdx.x) * 4;
    if (i >= n) return;
    float4 v = *reinterpret_cast<const float4*>(&X[i]);
    __nv_bfloat16 h0, h1, h2, h3, l0, l1, l2, l3;
    splitf(v.x, h0, l0); splitf(v.y, h1, l1);
    splitf(v.z, h2, l2); splitf(v.w, h3, l3);
    __nv_bfloat162 hp0 = {h0, h1}, hp1 = {h2, h3}, lp0 = {l0, l1}, lp1 = {l2, l3};
    *reinterpret_cast<__nv_bfloat162*>(&hi[i]) = hp0;
    *reinterpret_cast<__nv_bfloat162*>(&hi[i + 2]) = hp1;
    *reinterpret_cast<__nv_bfloat162*>(&lo[i]) = lp0;
    *reinterpret_cast<__nv_bfloat162*>(&lo[i + 2]) = lp1;
}

// ---------------------------------------------------------------------------
// split + transpose: W[K,N] fp32 -> T{hi,lo}[N,K] bf16
// ---------------------------------------------------------------------------
__global__ __launch_bounds__(256) void split_transpose_kernel(
    const float* __restrict__ W, __nv_bfloat16* __restrict__ Thi,
    __nv_bfloat16* __restrict__ Tlo, int K, int N)
{
    __shared__ float t[32][33];
    int tx = threadIdx.x, ty = threadIdx.y;
    int n0 = blockIdx.x * 32, k0 = blockIdx.y * 32;
#pragma unroll
    for (int i = 0; i < 4; i++)
        t[ty + 8 * i][tx] = W[(size_t)(k0 + ty + 8 * i) * N + n0 + tx];
    __syncthreads();
#pragma unroll
    for (int i = 0; i < 4; i++) {
        float v = t[tx][ty + 8 * i];
        __nv_bfloat16 h, l;
        splitf(v, h, l);
        size_t o = (size_t)(n0 + ty + 8 * i) * K + k0 + tx;
        Thi[o] = h;
        Tlo[o] = l;
    }
}

// ---------------------------------------------------------------------------
// prep_vt: transpose V hi/lo from qkv split -> Vt[b][d][s] (pure copy)
// block (32,8), grid (S/32, 128/32, B)
// ---------------------------------------------------------------------------
__global__ __launch_bounds__(256) void prep_vt(
    const __nv_bfloat16* __restrict__ qhi, const __nv_bfloat16* __restrict__ qlo,
    __nv_bfloat16* __restrict__ vthi, __nv_bfloat16* __restrict__ vtlo)
{
    __shared__ __nv_bfloat16 th[32][34], tl[32][34];
    int tx = threadIdx.x, ty = threadIdx.y;
    int s0 = blockIdx.x * 32, d0 = blockIdx.y * 32, b = blockIdx.z;
#pragma unroll
    for (int i = 0; i < 4; i++) {
        size_t src = (size_t)(b * SS + s0 + ty + 8 * i) * NQKV + HH * HDIM + HDIM + d0 + tx;
        th[ty + 8 * i][tx] = qhi[src];
        tl[ty + 8 * i][tx] = qlo[src];
    }
    __syncthreads();
#pragma unroll
    for (int i = 0; i < 4; i++) {
        size_t dst = (size_t)(b * HDIM + d0 + ty + 8 * i) * SS + s0 + tx;
        vthi[dst] = th[tx][ty + 8 * i];
        vtlo[dst] = tl[tx][ty + 8 * i];
    }
}

// ---------------------------------------------------------------------------
// wmma bf16 3-term split GEMM + bias. Output either f32 C or split (Chi,Clo).
// CTA tile 128x128, BK=32, 8 warps, cp.async double buffer, 2 CTAs/SM.
// ---------------------------------------------------------------------------
#define BK 32
#define LDT 40
#define TILE_HB (128 * LDT)
#define TILE_BYTES (TILE_HB * 2)
#define BUF_BYTES (4 * TILE_BYTES)
#define EPI_LD 136

template <bool SPLIT_OUT>
__global__ __launch_bounds__(256, 2)
void wmma_gemm_bias(const __nv_bfloat16* __restrict__ Ahi,
                    const __nv_bfloat16* __restrict__ Alo,
                    const __nv_bfloat16* __restrict__ Bhi,
                    const __nv_bfloat16* __restrict__ Blo,
                    const float* __restrict__ bias, float* __restrict__ C,
                    __nv_bfloat16* __restrict__ Chi, __nv_bfloat16* __restrict__ Clo,
                    int M, int N, int K)
{
    extern __shared__ char sm[];
    const uint32_t smb = smem_u32(sm);
    const int tid = threadIdx.x;
    const int wid = tid >> 5;
    const int ntile = blockIdx.x, mtile = blockIdx.y;

    const int warp_m = (wid >> 1) * 32;
    const int warp_n = (wid & 1) * 64;

    const __nv_bfloat16* srcs[4] = {
        Ahi + (size_t)mtile * 128 * K, Alo + (size_t)mtile * 128 * K,
        Bhi + (size_t)ntile * 128 * K, Blo + (size_t)ntile * 128 * K };

    auto issue_load = [&](int b, int k0) {
        const uint32_t bufb = smb + b * BUF_BYTES;
#pragma unroll
        for (int t = 0; t < 4; t++) {
            const __nv_bfloat16* s = srcs[t];
            const uint32_t tb = bufb + t * TILE_BYTES;
#pragma unroll
            for (int it = 0; it < 2; it++) {
                int idx = tid + it * 256;
                int row = idx >> 2;
                int ch = idx & 3;
                cp_async16(tb + (row * LDT + ch * 8) * 2,
                           s + (size_t)row * K + k0 + ch * 8);
            }
        }
        cp_commit();
    };

    wmma::fragment<wmma::accumulator, 16, 16, 16, float> acc[2][4];
#pragma unroll
    for (int i = 0; i < 2; i++)
#pragma unroll
        for (int j = 0; j < 4; j++) wmma::fill_fragment(acc[i][j], 0.0f);

    const int niter = K / BK;
    issue_load(0, 0);

    for (int iter = 0; iter < niter; iter++) {
        const int buf = iter & 1;
        if (iter + 1 < niter) {
            issue_load(buf ^ 1, (iter + 1) * BK);
            cp_wait<1>();
        } else {
            cp_wait<0>();
        }
        __syncthreads();

        const __nv_bfloat16* base = reinterpret_cast<const __nv_bfloat16*>(sm + buf * BUF_BYTES);
        const __nv_bfloat16* As_hi = base;
        const __nv_bfloat16* As_lo = base + TILE_HB;
        const __nv_bfloat16* Bs_hi = base + 2 * TILE_HB;
        const __nv_bfloat16* Bs_lo = base + 3 * TILE_HB;

#pragma unroll
        for (int kk = 0; kk < BK; kk += 16) {
            wmma::fragment<wmma::matrix_a, 16, 16, 16, __nv_bfloat16, wmma::row_major> ah[2], al[2];
#pragma unroll
            for (int i = 0; i < 2; i++) {
                wmma::load_matrix_sync(ah[i], As_hi + (warp_m + 16 * i) * LDT + kk, LDT);
                wmma::load_matrix_sync(al[i], As_lo + (warp_m + 16 * i) * LDT + kk, LDT);
            }
#pragma unroll
            for (int j = 0; j < 4; j++) {
                wmma::fragment<wmma::matrix_b, 16, 16, 16, __nv_bfloat16, wmma::col_major> bh, bl;
                wmma::load_matrix_sync(bh, Bs_hi + (warp_n + 16 * j) * LDT + kk, LDT);
                wmma::load_matrix_sync(bl, Bs_lo + (warp_n + 16 * j) * LDT + kk, LDT);
#pragma unroll
                for (int i = 0; i < 2; i++) {
                    wmma::mma_sync(acc[i][j], ah[i], bh, acc[i][j]);
                    wmma::mma_sync(acc[i][j], ah[i], bl, acc[i][j]);
                    wmma::mma_sync(acc[i][j], al[i], bh, acc[i][j]);
                }
            }
        }
        __syncthreads();
    }

    float* Cs = reinterpret_cast<float*>(sm);
#pragma unroll
    for (int i = 0; i < 2; i++)
#pragma unroll
        for (int j = 0; j < 4; j++)
            wmma::store_matrix_sync(Cs + (warp_m + 16 * i) * EPI_LD + warp_n + 16 * j,
                                    acc[i][j], EPI_LD, wmma::mem_row_major);
    __syncthreads();

#pragma unroll
    for (int it = 0; it < 16; it++) {
        int idx = tid + it * 256;
        int row = idx >> 5;
        int c4 = (idx & 31) * 4;
        float4 v = *reinterpret_cast<const float4*>(&Cs[row * EPI_LD + c4]);
        const int col0 = ntile * 128 + c4;
        v.x += bias[col0 + 0];
        v.y += bias[col0 + 1];
        v.z += bias[col0 + 2];
        v.w += bias[col0 + 3];
        const size_t o = (size_t)(mtile * 128 + row) * N + col0;
        if (SPLIT_OUT) {
            __nv_bfloat16 h0, h1, h2, h3, l0, l1, l2, l3;
            splitf(v.x, h0, l0); splitf(v.y, h1, l1);
            splitf(v.z, h2, l2); splitf(v.w, h3, l3);
            __nv_bfloat162 hp0 = {h0, h1}, hp1 = {h2, h3};
            __nv_bfloat162 lp0 = {l0, l1}, lp1 = {l2, l3};
            *reinterpret_cast<__nv_bfloat162*>(&Chi[o]) = hp0;
            *reinterpret_cast<__nv_bfloat162*>(&Chi[o + 2]) = hp1;
            *reinterpret_cast<__nv_bfloat162*>(&Clo[o]) = lp0;
            *reinterpret_cast<__nv_bfloat162*>(&Clo[o + 2]) = lp1;
        } else {
            *reinterpret_cast<float4*>(&C[o]) = v;
        }
    }
}

// ---------------------------------------------------------------------------
// MQA flash attention v4 — tensor-core mma m16n8k16, all loads via cp.async
// from pre-split arrays, K/V ping-pong overlap, split bf16 output.
// Block: 256 thr, 128 score rows (16 heads x 8 q), 128-key tiles.
// smem: Qhi/Qlo, Khi/Klo, Vthi/Vtlo  (6 x 128 x 136 halves = 204 KB)
// ---------------------------------------------------------------------------
#define ALD 136
#define ATILE (128 * ALD)

__global__ __launch_bounds__(256, 1) void mqa_attn_v4(
    const __nv_bfloat16* __restrict__ qhi, const __nv_bfloat16* __restrict__ qlo,
    const __nv_bfloat16* __restrict__ vthi, const __nv_bfloat16* __restrict__ vtlo,
    __nv_bfloat16* __restrict__ ohi, __nv_bfloat16* __restrict__ olo)
{
    extern __shared__ __nv_bfloat16 smh[];
    __nv_bfloat16* Qhi = smh;
    __nv_bfloat16* Qlo = smh + ATILE;
    __nv_bfloat16* Khi = smh + 2 * ATILE;
    __nv_bfloat16* Klo = smh + 3 * ATILE;
    __nv_bfloat16* Vhi = smh + 4 * ATILE;
    __nv_bfloat16* Vlo = smh + 5 * ATILE;
    const uint32_t smb = smem_u32(smh);
    const uint32_t oQhi = 0, oQlo = ATILE * 2, oKhi = 2 * ATILE * 2,
                   oKlo = 3 * ATILE * 2, oVhi = 4 * ATILE * 2, oVlo = 5 * ATILE * 2;

    const int tid = threadIdx.x;
    const int w = tid >> 5;
    const int lane = tid & 31;
    const int g = lane >> 2;
    const int t = lane & 3;
    const int b = blockIdx.y;
    const int q0 = blockIdx.x * 8;
    const float scale = 0.08838834764831845f;

    const int r_lo = w * 16 + g;

    // ---- async load Q (rows = h*8+qi) ----
#pragma unroll
    for (int it = 0; it < 8; ++it) {
        int idx = tid + it * 256;          // 0..2047
        int row = idx >> 4;                // 0..127
        int ch = idx & 15;                 // 16B chunk (8 halves)
        size_t src = (size_t)(b * SS + q0 + (row & 7)) * NQKV + (row >> 3) * HDIM + ch * 8;
        uint32_t d = (uint32_t)(row * ALD + ch * 8) * 2;
        cp_async16(smb + oQhi + d, qhi + src);
        cp_async16(smb + oQlo + d, qlo + src);
    }
    // ---- async load K(0) ----
    {
#pragma unroll
        for (int it = 0; it < 8; ++it) {
            int idx = tid + it * 256;
            int row = idx >> 4;
            int ch = idx & 15;
            size_t src = (size_t)(b * SS + row) * NQKV + HH * HDIM + ch * 8;
            uint32_t d = (uint32_t)(row * ALD + ch * 8) * 2;
            cp_async16(smb + oKhi + d, qhi + src);
            cp_async16(smb + oKlo + d, qlo + src);
        }
    }
    cp_commit();

    float m0 = -INFINITY, m1 = -INFINITY, l0s = 0.0f, l1s = 0.0f;
    float O[16][4];
#pragma unroll
    for (int j = 0; j < 16; j++)
#pragma unroll
        for (int c = 0; c < 4; c++) O[j][c] = 0.0f;

    const int ntiles = (q0 + 7) / 128 + 1;

    cp_wait<0>();
    __syncthreads();

    for (int tt = 0; tt < ntiles; ++tt) {
        const int t0 = tt * 128;

        // ---- issue V(tt) (overlaps with QK compute) ----
#pragma unroll
        for (int it = 0; it < 8; ++it) {
            int idx = tid + it * 256;
            int row = idx >> 4;            // dim
            int ch = idx & 15;
            size_t src = (size_t)(b * HDIM + row) * SS + t0 + ch * 8;
            uint32_t d = (uint32_t)(row * ALD + ch * 8) * 2;
            cp_async16(smb + oVhi + d, vthi + src);
            cp_async16(smb + oVlo + d, vtlo + src);
        }
        cp_commit();

        // ---- QK^T ----
        float s[16][4];
#pragma unroll
        for (int j = 0; j < 16; j++)
#pragma unroll
            for (int c = 0; c < 4; c++) s[j][c] = 0.0f;

#pragma unroll
        for (int k = 0; k < 8; ++k) {
            uint32_t ah[4], al[4];
            const int d0 = 16 * k + 2 * t;
            ah[0] = *reinterpret_cast<const uint32_t*>(&Qhi[r_lo * ALD + d0]);
            ah[1] = *reinterpret_cast<const uint32_t*>(&Qhi[(r_lo + 8) * ALD + d0]);
            ah[2] = *reinterpret_cast<const uint32_t*>(&Qhi[r_lo * ALD + d0 + 8]);
            ah[3] = *reinterpret_cast<const uint32_t*>(&Qhi[(r_lo + 8) * ALD + d0 + 8]);
            al[0] = *reinterpret_cast<const uint32_t*>(&Qlo[r_lo * ALD + d0]);
            al[1] = *reinterpret_cast<const uint32_t*>(&Qlo[(r_lo + 8) * ALD + d0]);
            al[2] = *reinterpret_cast<const uint32_t*>(&Qlo[r_lo * ALD + d0 + 8]);
            al[3] = *reinterpret_cast<const uint32_t*>(&Qlo[(r_lo + 8) * ALD + d0 + 8]);
#pragma unroll
            for (int j = 0; j < 16; ++j) {
                const int kr = (8 * j + g) * ALD + d0;
                uint32_t bh0 = *reinterpret_cast<const uint32_t*>(&Khi[kr]);
                uint32_t bh1 = *reinterpret_cast<const uint32_t*>(&Khi[kr + 8]);
                uint32_t bl0 = *reinterpret_cast<const uint32_t*>(&Klo[kr]);
                uint32_t bl1 = *reinterpret_cast<const uint32_t*>(&Klo[kr + 8]);
                mma_bf16(s[j], ah, bh0, bh1);
                mma_bf16(s[j], ah, bl0, bl1);
                mma_bf16(s[j], al, bh0, bh1);
            }
        }

        cp_wait<0>();        // V(tt) arrived; also gates K overwrite below
        __syncthreads();     // all warps finished QK

        // ---- scale + causal mask ----
#pragma unroll
        for (int j = 0; j < 16; ++j)
#pragma unroll
            for (int c = 0; c < 4; c++) s[j][c] *= scale;

        if (tt == ntiles - 1) {
#pragma unroll
            for (int j = 0; j < 16; ++j) {
                const int col = t0 + 8 * j + 2 * t;
                if (col > q0 + g)     { s[j][0] = -1e30f; s[j][2] = -1e30f; }
                if (col + 1 > q0 + g) { s[j][1] = -1e30f; s[j][3] = -1e30f; }
            }
        }

        // ---- online softmax ----
        float mx0 = -INFINITY, mx1 = -INFINITY;
#pragma unroll
        for (int j = 0; j < 16; ++j) {
            mx0 = fmaxf(mx0, fmaxf(s[j][0], s[j][1]));
            mx1 = fmaxf(mx1, fmaxf(s[j][2], s[j][3]));
        }
        mx0 = fmaxf(mx0, __shfl_xor_sync(0xffffffffu, mx0, 1));
        mx0 = fmaxf(mx0, __shfl_xor_sync(0xffffffffu, mx0, 2));
        mx1 = fmaxf(mx1, __shfl_xor_sync(0xffffffffu, mx1, 1));
        mx1 = fmaxf(mx1, __shfl_xor_sync(0xffffffffu, mx1, 2));
        const float mn0 = fmaxf(m0, mx0), mn1 = fmaxf(m1, mx1);
        const float corr0 = __expf(m0 - mn0), corr1 = __expf(m1 - mn1);
        m0 = mn0; m1 = mn1;

        float sum0 = 0.0f, sum1 = 0.0f;
#pragma unroll
        for (int j = 0; j < 16; ++j) {
            s[j][0] = __expf(s[j][0] - mn0);
            s[j][1] = __expf(s[j][1] - mn0);
            s[j][2] = __expf(s[j][2] - mn1);
            s[j][3] = __expf(s[j][3] - mn1);
            sum0 += s[j][0] + s[j][1];
            sum1 += s[j][2] + s[j][3];
        }
        sum0 += __shfl_xor_sync(0xffffffffu, sum0, 1);
        sum0 += __shfl_xor_sync(0xffffffffu, sum0, 2);
        sum1 += __shfl_xor_sync(0xffffffffu, sum1, 1);
        sum1 += __shfl_xor_sync(0xffffffffu, sum1, 2);
        l0s = l0s * corr0 + sum0;
        l1s = l1s * corr1 + sum1;

#pragma unroll
        for (int j = 0; j < 16; ++j) {
            O[j][0] *= corr0; O[j][1] *= corr0;
            O[j][2] *= corr1; O[j][3] *= corr1;
        }

        // ---- repack P -> bf16 hi/lo A-fragments ----
        uint32_t pah[8][4], pal[8][4];
#pragma unroll
        for (int ss = 0; ss < 8; ++ss) {
#pragma unroll
            for (int c = 0; c < 4; ++c) {
                float va = s[2 * ss][c], vb = s[2 * ss + 1][c];
                __nv_bfloat16 ha, la, hb, lb;
                splitf(va, ha, la);
                splitf(vb, hb, lb);
                // A-frag reg order: [0]=rows g cols 2t,2t+1 (k lo); [1]=row g+8;
                // [2]=rows g cols +8 (k hi); [3]=row g+8 cols +8
                int r = (c & 1) ? -1 : 0;  // placeholder (not used)
                (void)r;
                // c: 0 -> (row g, cols 2t/2t+1): but s[j][c] maps c0,c1 = row g cols 2t,2t+1
                // handled below
                if (c == 0) { pah[ss][0] = 0; }  // filled after loop
            }
        }
        // explicit repack (matching v3 proven mapping)
#pragma unroll
        for (int ss = 0; ss < 8; ++ss) {
            __nv_bfloat16 h, l;
            float h00, q00, h01, q01, h10, q10, h11, q11;
            float h20, q20, h21, q21, h30, q30, h31, q31;
            splitf(s[2 * ss][0], h, l); h00 = __bfloat162float(h); q00 = __bfloat162float(l);
            splitf(s[2 * ss][1], h, l); h01 = __bfloat162float(h); q01 = __bfloat162float(l);
            splitf(s[2 * ss][2], h, l); h10 = __bfloat162float(h); q10 = __bfloat162float(l);
            splitf(s[2 * ss][3], h, l); h11 = __bfloat162float(h); q11 = __bfloat162float(l);
            splitf(s[2 * ss + 1][0], h, l); h20 = __bfloat162float(h); q20 = __bfloat162float(l);
            splitf(s[2 * ss + 1][1], h, l); h21 = __bfloat162float(h); q21 = __bfloat162float(l);
            splitf(s[2 * ss + 1][2], h, l); h30 = __bfloat162float(h); q30 = __bfloat162float(l);
            splitf(s[2 * ss + 1][3], h, l); h31 = __bfloat162float(h); q31 = __bfloat162float(l);
            pah[ss][0] = pack2(h00, h01); pal[ss][0] = pack2(q00, q01);
            pah[ss][1] = pack2(h10, h11); pal[ss][1] = pack2(q10, q11);
            pah[ss][2] = pack2(h20, h21); pal[ss][2] = pack2(q20, q21);
            pah[ss][3] = pack2(h30, h31); pal[ss][3] = pack2(q30, q31);
        }

        // ---- issue K(tt+1) (overlaps with PV compute) ----
        if (tt + 1 < ntiles) {
            const int t1 = t0 + 128;
#pragma unroll
            for (int it = 0; it < 8; ++it) {
                int idx = tid + it * 256;
                int row = idx >> 4;
                int ch = idx & 15;
                size_t src = (size_t)(b * SS + t1 + row) * NQKV + HH * HDIM + ch * 8;
                uint32_t d = (uint32_t)(row * ALD + ch * 8) * 2;
                cp_async16(smb + oKhi + d, qhi + src);
                cp_async16(smb + oKlo + d, qlo + src);
            }
            cp_commit();
        }

        // ---- PV ----
#pragma unroll
        for (int ss = 0; ss < 8; ++ss) {
            const int kb = 16 * ss + 2 * t;
#pragma unroll
            for (int j2 = 0; j2 < 16; ++j2) {
                const int vr = (8 * j2 + g) * ALD + kb;
                uint32_t bh0 = *reinterpret_cast<const uint32_t*>(&Vhi[vr]);
                uint32_t bh1 = *reinterpret_cast<const uint32_t*>(&Vhi[vr + 8]);
                uint32_t bl0 = *reinterpret_cast<const uint32_t*>(&Vlo[vr]);
                uint32_t bl1 = *reinterpret_cast<const uint32_t*>(&Vlo[vr + 8]);
                mma_bf16(O[j2], pah[ss], bh0, bh1);
                mma_bf16(O[j2], pah[ss], bl0, bl1);
                mma_bf16(O[j2], pal[ss], bh0, bh1);
            }
        }

        if (tt + 1 < ntiles) {
            cp_wait<0>();
            __syncthreads();   // all warps done PV; K(tt+1) in smem
        }
    }

    // ---- epilogue: normalize + split-store bf16 hi/lo ----
    const float inv0 = 1.0f / l0s, inv1 = 1.0f / l1s;
    const size_t row0 = (size_t)(b * SS + q0 + g) * DD;
    const int h_lo = 2 * w, h_hi = 2 * w + 1;
#pragma unroll
    for (int j2 = 0; j2 < 16; ++j2) {
        const int d = 8 * j2 + 2 * t;
        float v00 = O[j2][0] * inv0, v01 = O[j2][1] * inv0;
        float v10 = O[j2][2] * inv1, v11 = O[j2][3] * inv1;
        __nv_bfloat16 h0, l0, h1, l1;
        splitf(v00, h0, l0); splitf(v01, h1, l1);
        __nv_bfloat162 hp = {h0, h1}, lp = {l0, l1};
        *reinterpret_cast<__nv_bfloat162*>(&ohi[row0 + h_lo * HDIM + d]) = hp;
        *reinterpret_cast<__nv_bfloat162*>(&olo[row0 + h_lo * HDIM + d]) = lp;
        splitf(v10, h0, l0); splitf(v11, h1, l1);
        __nv_bfloat162 hp2 = {h0, h1}, lp2 = {l0, l1};
        *reinterpret_cast<__nv_bfloat162*>(&ohi[row0 + h_hi * HDIM + d]) = hp2;
        *reinterpret_cast<__nv_bfloat162*>(&olo[row0 + h_hi * HDIM + d]) = lp2;
    }
}

// ---------------------------------------------------------------------------
extern "C" void kernel_launch(void* const* d_in, const int* in_sizes, int n_in,
                              void* d_out, int out_size)
{
    const float* hidden = (const float*)d_in[0];
    const float* W_attn = (const float*)d_in[1];
    const float* b_attn = (const float*)d_in[2];
    const float* W_proj = (const float*)d_in[3];
    const float* b_proj = (const float*)d_in[4];
    float* out = (float*)d_out;

    __nv_bfloat16 *qkvhi, *qkvlo, *Xhi, *Xlo, *WaThi, *WaTlo, *WpThi, *WpTlo;
    __nv_bfloat16 *AThi, *ATlo, *Vthi, *Vtlo;
    cudaGetSymbolAddress((void**)&qkvhi, g_qkvhi);
    cudaGetSymbolAddress((void**)&qkvlo, g_qkvlo);
    cudaGetSymbolAddress((void**)&Xhi, g_Xhi);
    cudaGetSymbolAddress((void**)&Xlo, g_Xlo);
    cudaGetSymbolAddress((void**)&WaThi, g_WaThi);
    cudaGetSymbolAddress((void**)&WaTlo, g_WaTlo);
    cudaGetSymbolAddress((void**)&WpThi, g_WpThi);
    cudaGetSymbolAddress((void**)&WpTlo, g_WpTlo);
    cudaGetSymbolAddress((void**)&AThi, g_AThi);
    cudaGetSymbolAddress((void**)&ATlo, g_ATlo);
    cudaGetSymbolAddress((void**)&Vthi, g_Vthi);
    cudaGetSymbolAddress((void**)&Vtlo, g_Vtlo);

    const int attn_smem = 6 * ATILE * sizeof(__nv_bfloat16);      // 208,896 B
    const int gemm_smem = 2 * BUF_BYTES;                          // 81,920 B
    cudaFuncSetAttribute(mqa_attn_v4,
                         cudaFuncAttributeMaxDynamicSharedMemorySize, attn_smem);
    cudaFuncSetAttribute(wmma_gemm_bias<true>,
                         cudaFuncAttributeMaxDynamicSharedMemorySize, gemm_smem);
    cudaFuncSetAttribute(wmma_gemm_bias<false>,
                         cudaFuncAttributeMaxDynamicSharedMemorySize, gemm_smem);

    // 0) input splits
    split_kernel<<<MM * DD / 1024, 256>>>(hidden, Xhi, Xlo, MM * DD);
    {
        dim3 g(NQKV / 32, DD / 32), blk(32, 8);
        split_transpose_kernel<<<g, blk>>>(W_attn, WaThi, WaTlo, DD, NQKV);
    }
    {
        dim3 g(DD / 32, DD / 32), blk(32, 8);
        split_transpose_kernel<<<g, blk>>>(W_proj, WpThi, WpTlo, DD, DD);
    }

    // 1) QKV GEMM -> split bf16 output
    {
        dim3 grid(NQKV / 128, MM / 128);
        wmma_gemm_bias<true><<<grid, 256, gemm_smem>>>(
            Xhi, Xlo, WaThi, WaTlo, b_attn, nullptr, qkvhi, qkvlo, MM, NQKV, DD);
    }

    // 1b) transpose V (pure bf16 copy)
    {
        dim3 g(SS / 32, HDIM / 32, BB), blk(32, 8);
        prep_vt<<<g, blk>>>(qkvhi, qkvlo, Vthi, Vtlo);
    }

    // 2) MQA causal flash attention -> split bf16 output
    {
        dim3 grid(SS / 8, BB);
        mqa_attn_v4<<<grid, 256, attn_smem>>>(qkvhi, qkvlo, Vthi, Vtlo, AThi, ATlo);
    }

    // 3) Projection GEMM -> f32 final output
    {
        dim3 grid(DD / 128, MM / 128);
        wmma_gemm_bias<false><<<grid, 256, gemm_smem>>>(
            AThi, ATlo, WpThi, WpTlo, b_proj, out, nullptr, nullptr, MM, DD, DD);
    }
}